// round 7
// baseline (speedup 1.0000x reference)
#include <cuda_runtime.h>
#include <cstdint>

#define Bq 4
#define Cq 64
#define Hq 128
#define Wq 128
#define HWq (Hq*Wq)
#define CHWq (Cq*HWq)
#define KK 7
#define TAPS 49
#define NKB 72                 // K-blocks: 9 taps * 8 ci-octets, k8 each
#define WB_KB 512              // floats per k-block (8 nb * 32 lane * 2)
#define WB_HALF (NKB*WB_KB)    // 36864 floats (hi plane size)
#define WB_CONV (2*WB_HALF)    // 73728 floats per conv (hi+lo)

// scratch (allocation-free rule: __device__ globals)
__device__ float g_rx [Bq*CHWq];
__device__ float g_b1f[Bq*CHWq];
__device__ float g_b1m[Bq*CHWq];
__device__ float g_b2f[Bq*CHWq];
__device__ float g_b2m[Bq*CHWq];
__device__ float g_lp [Bq*TAPS*HWq];
__device__ float g_wB [4*WB_CONV];   // B fragments, per-lane order, hi|lo

// ---------------------------------------------------------------------------
// helpers
// ---------------------------------------------------------------------------
__device__ __forceinline__ uint32_t tf32_hi(float v) {
    uint32_t r; asm("cvt.rna.tf32.f32 %0, %1;" : "=r"(r) : "f"(v)); return r;
}
__device__ __forceinline__ void cp16(void* dst, const void* src) {
    unsigned d = (unsigned)__cvta_generic_to_shared(dst);
    asm volatile("cp.async.ca.shared.global [%0], [%1], 16;" :: "r"(d), "l"(src));
}
#define CP_COMMIT asm volatile("cp.async.commit_group;")
#define CP_WAIT0  asm volatile("cp.async.wait_group 0;")

__device__ __forceinline__ void mma_tf32(float d[4],
    uint32_t a0, uint32_t a1, uint32_t a2, uint32_t a3,
    uint32_t b0, uint32_t b1)
{
    asm volatile(
        "mma.sync.aligned.m16n8k8.row.col.f32.tf32.tf32.f32 "
        "{%0,%1,%2,%3}, {%4,%5,%6,%7}, {%8,%9}, {%0,%1,%2,%3};"
        : "+f"(d[0]), "+f"(d[1]), "+f"(d[2]), "+f"(d[3])
        : "r"(a0), "r"(a1), "r"(a2), "r"(a3), "r"(b0), "r"(b1));
}

// ---------------------------------------------------------------------------
// prep kernels
// ---------------------------------------------------------------------------
__global__ void prep_relu_kernel(const float* __restrict__ x, float* __restrict__ rx)
{
    int i = blockIdx.x*256 + threadIdx.x;
    float4 v = ((const float4*)x)[i];
    v.x = fmaxf(v.x, 0.f); v.y = fmaxf(v.y, 0.f);
    v.z = fmaxf(v.z, 0.f); v.w = fmaxf(v.w, 0.f);
    ((float4*)rx)[i] = v;
}

// Pack weights into per-lane B-fragment order, tf32 hi/lo split.
// B frag (m16n8k8 col): b0 = B[k=lane%4][n=lane/4], b1 = B[k+4][n]
// Our k-block kb = tap*8 + oct;  k-in-block kl;  ci = oct*8 + kl;  n = co.
__global__ void prep_wt_kernel(const float* __restrict__ w0, const float* __restrict__ w1,
                               const float* __restrict__ w2, const float* __restrict__ w3,
                               float* __restrict__ wB)
{
    int i = blockIdx.x*256 + threadIdx.x;    // 0 .. 4*72*8*32-1
    int conv = i / (NKB*8*32);
    int r    = i - conv*(NKB*8*32);
    int kb   = r / (8*32);
    int r2   = r - kb*(8*32);
    int nb   = r2 >> 5;
    int lane = r2 & 31;

    int tap = kb >> 3, oct = kb & 7;
    int n   = nb*8 + (lane >> 2);
    int kl  = lane & 3;
    int ci0 = oct*8 + kl;

    const float* w = (conv == 0) ? w0 : (conv == 1) ? w1 : (conv == 2) ? w2 : w3;
    float v0 = w[(n*Cq + ci0    )*9 + tap];
    float v1 = w[(n*Cq + ci0 + 4)*9 + tap];

    uint32_t h0 = tf32_hi(v0), h1 = tf32_hi(v1);
    uint32_t l0 = tf32_hi(v0 - __uint_as_float(h0));
    uint32_t l1 = tf32_hi(v1 - __uint_as_float(h1));

    float* base = wB + conv*WB_CONV + kb*WB_KB + (nb*32 + lane)*2;
    base[0] = __uint_as_float(h0);
    base[1] = __uint_as_float(h1);
    base[WB_HALF]     = __uint_as_float(l0);
    base[WB_HALF + 1] = __uint_as_float(l1);
}

// ---------------------------------------------------------------------------
// conv3x3 via mma.sync tf32 (3-pass split precision).
// One CTA = one output row of one (path,batch): D[128 px][64 co].
// grid = (Hq, 2*Bq). 8 warps, warp w owns px block [16w, 16w+16).
// A smem layout: [px][10] floats, element (px,kl): pos = px*10 + (kl%4)*2 + kl/4
//   -> frag (a0,a2) = float2 at px*10 + (lane%4)*2 ; (a1,a3) at px+8.
// ---------------------------------------------------------------------------
#define APAD 10
template<bool RELU_OUT>
__global__ __launch_bounds__(256, 2)
void conv_mma_kernel(const float* __restrict__ inA, const float* __restrict__ inB,
                     const float* __restrict__ wBA, const float* __restrict__ wBB,
                     const float* __restrict__ biasA, const float* __restrict__ biasB,
                     float* __restrict__ outA, float* __restrict__ outB)
{
    __shared__ float sAh[2][128*APAD];
    __shared__ float sAl[2][128*APAD];
    __shared__ float sBh[2][8*32*2];
    __shared__ float sBl[2][8*32*2];

    const int y  = blockIdx.x;
    const int z  = blockIdx.y;
    const int b  = z & 3;
    const bool pB = (z >= 4);
    const float* in   = (pB ? inB  : inA) + b*CHWq;
    const float* wB   =  pB ? wBB  : wBA;
    const float* bias =  pB ? biasB : biasA;
    float*       out  = (pB ? outB : outA) + b*CHWq;

    const int tid  = threadIdx.x;
    const int wid  = tid >> 5;
    const int lane = tid & 31;

    // staging role: g selects kl half (0..3 or 4..7), px = tid & 127
    const int sg  = tid >> 7;          // 0 or 1
    const int spx = tid & 127;

    float d[8][4];
#pragma unroll
    for (int nb = 0; nb < 8; nb++)
#pragma unroll
        for (int r = 0; r < 4; r++) d[nb][r] = 0.f;

    // ---- A preload (global -> regs), kl = sg*4 + i ----
    float v[4];
    auto preloadA = [&](int kb) {
        int tap = kb >> 3, oct = kb & 7;
        int dy = tap/3, dx = tap - dy*3;
        int yin = y + dy - 1;
        int gx  = spx + dx - 1;
        bool ok = (yin >= 0) & (yin < Hq) & (gx >= 0) & (gx < Wq);
        const float* p = in + (oct*8 + sg*4)*HWq + yin*Wq + gx;
#pragma unroll
        for (int i = 0; i < 4; i++)
            v[i] = ok ? __ldg(p + i*HWq) : 0.f;
    };
    // ---- A split + store to smem ----
    auto storeA = [&](int buf) {
#pragma unroll
        for (int i = 0; i < 4; i++) {
            uint32_t hi = tf32_hi(v[i]);
            uint32_t lo = tf32_hi(v[i] - __uint_as_float(hi));
            int pos = spx*APAD + i*2 + sg;
            sAh[buf][pos] = __uint_as_float(hi);
            sAl[buf][pos] = __uint_as_float(lo);
        }
    };
    // ---- B staging via cp.async ----
    auto stageB = [&](int buf, int kb) {
        if (tid < 128)
            cp16(&sBh[buf][tid*4], (const float4*)(wB + kb*WB_KB) + tid);
        else
            cp16(&sBl[buf][(tid-128)*4],
                 (const float4*)(wB + WB_HALF + kb*WB_KB) + (tid-128));
        CP_COMMIT;
    };

    preloadA(0);
    stageB(0, 0);
    storeA(0);
    CP_WAIT0;
    __syncthreads();

    const int m    = wid << 4;          // warp's px base
    const int arow = (m + (lane >> 2))*APAD + (lane & 3)*2;

    for (int kb = 0; kb < NKB; kb++) {
        const int buf = kb & 1;
        if (kb + 1 < NKB) { stageB(buf ^ 1, kb + 1); preloadA(kb + 1); }

        // A frags (hi and lo)
        float2 f02h = *(float2*)&sAh[buf][arow];
        float2 f13h = *(float2*)&sAh[buf][arow + 8*APAD];
        float2 f02l = *(float2*)&sAl[buf][arow];
        float2 f13l = *(float2*)&sAl[buf][arow + 8*APAD];
        uint32_t ah0 = __float_as_uint(f02h.x), ah2 = __float_as_uint(f02h.y);
        uint32_t ah1 = __float_as_uint(f13h.x), ah3 = __float_as_uint(f13h.y);
        uint32_t al0 = __float_as_uint(f02l.x), al2 = __float_as_uint(f02l.y);
        uint32_t al1 = __float_as_uint(f13l.x), al3 = __float_as_uint(f13l.y);

#pragma unroll
        for (int nb = 0; nb < 8; nb++) {
            float2 bh = *(float2*)&sBh[buf][(nb*32 + lane)*2];
            float2 bl = *(float2*)&sBl[buf][(nb*32 + lane)*2];
            uint32_t bh0 = __float_as_uint(bh.x), bh1 = __float_as_uint(bh.y);
            uint32_t bl0 = __float_as_uint(bl.x), bl1 = __float_as_uint(bl.y);
            mma_tf32(d[nb], ah0, ah1, ah2, ah3, bh0, bh1);   // hi*hi
            mma_tf32(d[nb], al0, al1, al2, al3, bh0, bh1);   // lo*hi
            mma_tf32(d[nb], ah0, ah1, ah2, ah3, bl0, bl1);   // hi*lo
        }

        if (kb + 1 < NKB) { storeA(buf ^ 1); CP_WAIT0; }
        __syncthreads();
    }

    // epilogue: D frag -> global.  row = lane/4 (+8), col = 2*(lane%4) (+1)
    const int row  = lane >> 2;
    const int colb = (lane & 3) << 1;
    float* op = out + y*Wq + m + row;
#pragma unroll
    for (int nb = 0; nb < 8; nb++) {
#pragma unroll
        for (int r = 0; r < 4; r++) {
            int co = nb*8 + colb + (r & 1);
            int px_off = (r >> 1) << 3;     // +8 for r=2,3
            float val = d[nb][r] + __ldg(bias + co);
            if (RELU_OUT) val = fmaxf(val, 0.f);
            op[co*HWq + px_off] = val;
        }
    }
}

// ---------------------------------------------------------------------------
// local_filter_path: conv1x1(64->64) -> relu -> conv1x1(64->49) -> normalize
// ---------------------------------------------------------------------------
__global__ __launch_bounds__(256, 1)
void lp_kernel(const float* __restrict__ kf,
               const float* __restrict__ w1, const float* __restrict__ b1,
               const float* __restrict__ w2, const float* __restrict__ b2,
               float* __restrict__ lp)
{
    __shared__ float s_w1[64*64];
    __shared__ float s_w2[64*52];
    __shared__ float s_b1[64];
    __shared__ float s_b2[49];
    const int tid = threadIdx.x;

    for (int i = tid; i < 64*64; i += 256) {
        int ci = i >> 6, co = i & 63;
        s_w1[i] = w1[co*64 + ci];
    }
    for (int i = tid; i < 64*49; i += 256) {
        int ci = i / 49, k = i - ci*49;
        s_w2[ci*52 + k] = w2[k*64 + ci];
    }
    if (tid < 64) s_b1[tid] = b1[tid];
    if (tid < 49) s_b2[tid] = b2[tid];
    __syncthreads();

    const int p  = blockIdx.x*256 + tid;
    const int b  = p >> 14;
    const int hw = p & (HWq-1);
    const float* kfp = kf + b*CHWq + hw;

    float h[64];
#pragma unroll
    for (int c = 0; c < 64; c++) h[c] = s_b1[c];
    for (int ci = 0; ci < 64; ci++) {
        float xv = kfp[ci*HWq];
#pragma unroll
        for (int co = 0; co < 64; co++)
            h[co] = fmaf(s_w1[ci*64 + co], xv, h[co]);
    }
#pragma unroll
    for (int c = 0; c < 64; c++) h[c] = fmaxf(h[c], 0.f);

    float o[TAPS];
#pragma unroll
    for (int k = 0; k < TAPS; k++) o[k] = s_b2[k];
    for (int ci = 0; ci < 64; ci++) {
        float hv = h[ci];
#pragma unroll
        for (int k = 0; k < TAPS; k++)
            o[k] = fmaf(s_w2[ci*52 + k], hv, o[k]);
    }
    float m = 0.f;
#pragma unroll
    for (int k = 0; k < TAPS; k++) m += o[k];
    m *= (1.0f/49.0f);

    float* lpp = lp + b*TAPS*HWq + hw;
#pragma unroll
    for (int k = 0; k < TAPS; k++)
        lpp[k*HWq] = o[k] - m + (1.0f/49.0f);
}

// ---------------------------------------------------------------------------
// dynamic 7x7 local conv + residual; feat = fp*mp computed on the fly.
// ---------------------------------------------------------------------------
#define TILE 16
#define LC_CG 8
#define LC_CPB (Cq/LC_CG)
__global__ __launch_bounds__(256, 2)
void local_conv_kernel(const float* __restrict__ x,
                       const float* __restrict__ fp, const float* __restrict__ mp,
                       const float* __restrict__ lp, float* __restrict__ out)
{
    __shared__ float s_f[22][24];
    const int bz = blockIdx.z;
    const int b  = bz >> 3;
    const int c0 = (bz & 7) * LC_CPB;
    const int x0 = blockIdx.x * TILE;
    const int y0 = blockIdx.y * TILE;
    const int tid = threadIdx.x;
    const int tx = tid & 15, ty = tid >> 4;
    const int y = y0 + ty, xx = x0 + tx;

    float kl[TAPS];
    const float* lpp = lp + b*TAPS*HWq + y*Wq + xx;
#pragma unroll
    for (int k = 0; k < TAPS; k++) kl[k] = lpp[k*HWq];

    const float* fpb = fp + b*CHWq;
    const float* mpb = mp + b*CHWq;
    const float* xb  = x  + b*CHWq;
    float*       ob  = out + b*CHWq;

    for (int ci = 0; ci < LC_CPB; ci++) {
        const int c = c0 + ci;
        __syncthreads();
        for (int i = tid; i < 22*22; i += 256) {
            int r  = i / 22;
            int cc = i - r*22;
            int gy = y0 + r - 3, gx = x0 + cc - 3;
            float v = 0.f;
            if (gy >= 0 && gy < Hq && gx >= 0 && gx < Wq) {
                int off = c*HWq + gy*Wq + gx;
                v = fpb[off] * mpb[off];
            }
            s_f[r][cc] = v;
        }
        __syncthreads();
        float acc = 0.f;
#pragma unroll
        for (int dy = 0; dy < KK; dy++)
#pragma unroll
            for (int dx = 0; dx < KK; dx++)
                acc = fmaf(s_f[ty+dy][tx+dx], kl[dy*KK+dx], acc);
        ob[c*HWq + y*Wq + xx] = xb[c*HWq + y*Wq + xx] + acc;
    }
}

// ---------------------------------------------------------------------------
extern "C" void kernel_launch(void* const* d_in, const int* in_sizes, int n_in,
                              void* d_out, int out_size)
{
    const float* x   = (const float*)d_in[0];
    const float* kf  = (const float*)d_in[1];
    const float* fw1 = (const float*)d_in[2];
    const float* fb1 = (const float*)d_in[3];
    const float* fw2 = (const float*)d_in[4];
    const float* fb2 = (const float*)d_in[5];
    const float* mw1 = (const float*)d_in[6];
    const float* mb1 = (const float*)d_in[7];
    const float* mw2 = (const float*)d_in[8];
    const float* mb2 = (const float*)d_in[9];
    const float* lw1 = (const float*)d_in[10];
    const float* lb1 = (const float*)d_in[11];
    const float* lw2 = (const float*)d_in[12];
    const float* lb2 = (const float*)d_in[13];
    float* out = (float*)d_out;

    float *rxp, *b1fp, *b1mp, *b2fp, *b2mp, *lpp, *wBp;
    cudaGetSymbolAddress((void**)&rxp,  g_rx);
    cudaGetSymbolAddress((void**)&b1fp, g_b1f);
    cudaGetSymbolAddress((void**)&b1mp, g_b1m);
    cudaGetSymbolAddress((void**)&b2fp, g_b2f);
    cudaGetSymbolAddress((void**)&b2mp, g_b2m);
    cudaGetSymbolAddress((void**)&lpp,  g_lp);
    cudaGetSymbolAddress((void**)&wBp,  g_wB);

    dim3 cblk(256);
    prep_relu_kernel<<<(Bq*CHWq/4)/256, cblk>>>(x, rxp);
    prep_wt_kernel<<<(4*NKB*8*32)/256, cblk>>>(fw1, fw2, mw1, mw2, wBp);
    lp_kernel<<<(Bq*HWq)/256, cblk>>>(kf, lw1, lb1, lw2, lb2, lpp);

    dim3 tgrid(Hq, 2*Bq);   // 128 rows x (2 paths * 4 batch) = 1024 CTAs
    const float* wf1 = wBp + 0*WB_CONV;
    const float* wf2 = wBp + 1*WB_CONV;
    const float* wm1 = wBp + 2*WB_CONV;
    const float* wm2 = wBp + 3*WB_CONV;

    conv_mma_kernel<true><<<tgrid, cblk>>>(
        rxp, kf, wf1, wm1, fb1, mb1, b1fp, b1mp);
    conv_mma_kernel<false><<<tgrid, cblk>>>(
        b1fp, b1mp, wf2, wm2, fb2, mb2, b2fp, b2mp);

    dim3 lgrid(Wq/TILE, Hq/TILE, Bq*LC_CG);
    local_conv_kernel<<<lgrid, cblk>>>(x, b2fp, b2mp, lpp, out);
}

// round 8
// speedup vs baseline: 1.1407x; 1.1407x over previous
#include <cuda_runtime.h>
#include <cstdint>

#define Bq 4
#define Cq 64
#define Hq 128
#define Wq 128
#define HWq (Hq*Wq)
#define CHWq (Cq*HWq)
#define KK 7
#define TAPS 49
#define NGRP 24                 // (dy 3) x (oct 8)
#define NKB  72                 // NGRP * 3 dx
#define WB4_CONV (NKB*256)      // float4 per conv: 72 kb * 8 nb * 32 lane

// scratch (allocation-free rule: __device__ globals)
__device__ float  g_rx [Bq*CHWq];
__device__ float  g_b1f[Bq*CHWq];
__device__ float  g_b1m[Bq*CHWq];
__device__ float  g_b2f[Bq*CHWq];
__device__ float  g_b2m[Bq*CHWq];
__device__ float  g_lp [Bq*TAPS*HWq];
__device__ float4 g_wB4[4*WB4_CONV];   // packed B frags (h0,h1,l0,l1)

// ---------------------------------------------------------------------------
__device__ __forceinline__ uint32_t tf32_hi(float v) {
    uint32_t r; asm("cvt.rna.tf32.f32 %0, %1;" : "=r"(r) : "f"(v)); return r;
}
__device__ __forceinline__ void cp16(void* dst, const void* src) {
    unsigned d = (unsigned)__cvta_generic_to_shared(dst);
    asm volatile("cp.async.ca.shared.global [%0], [%1], 16;" :: "r"(d), "l"(src));
}
#define CP_COMMIT asm volatile("cp.async.commit_group;")
#define CP_WAIT0  asm volatile("cp.async.wait_group 0;")

__device__ __forceinline__ void mma_tf32(float d[4], const uint32_t a[4],
                                         uint32_t b0, uint32_t b1)
{
    asm volatile(
        "mma.sync.aligned.m16n8k8.row.col.f32.tf32.tf32.f32 "
        "{%0,%1,%2,%3}, {%4,%5,%6,%7}, {%8,%9}, {%0,%1,%2,%3};"
        : "+f"(d[0]), "+f"(d[1]), "+f"(d[2]), "+f"(d[3])
        : "r"(a[0]), "r"(a[1]), "r"(a[2]), "r"(a[3]), "r"(b0), "r"(b1));
}

// ---------------------------------------------------------------------------
// prep kernels
// ---------------------------------------------------------------------------
__global__ void prep_relu_kernel(const float* __restrict__ x, float* __restrict__ rx)
{
    int i = blockIdx.x*256 + threadIdx.x;
    float4 v = ((const float4*)x)[i];
    v.x = fmaxf(v.x, 0.f); v.y = fmaxf(v.y, 0.f);
    v.z = fmaxf(v.z, 0.f); v.w = fmaxf(v.w, 0.f);
    ((float4*)rx)[i] = v;
}

// Pack weights: kb = (dy*8+oct)*3 + dx, tap = dy*3+dx.
// frag: b0 = B[k=lane%4][n], b1 = B[k+4][n]; ci = oct*8 + k.
// float4 = (b0_hi, b1_hi, b0_lo, b1_lo)
__global__ void prep_wt_kernel(const float* __restrict__ w0, const float* __restrict__ w1,
                               const float* __restrict__ w2, const float* __restrict__ w3,
                               float4* __restrict__ wB4)
{
    int i = blockIdx.x*256 + threadIdx.x;    // 0 .. 4*72*256-1
    int conv = i / WB4_CONV;
    int r    = i - conv*WB4_CONV;
    int kb   = r >> 8;
    int r2   = r & 255;
    int nb   = r2 >> 5;
    int lane = r2 & 31;

    int g  = kb / 3, dx = kb - g*3;
    int dy = g >> 3, oct = g & 7;
    int tap = dy*3 + dx;
    int n   = nb*8 + (lane >> 2);
    int ci0 = oct*8 + (lane & 3);

    const float* w = (conv == 0) ? w0 : (conv == 1) ? w1 : (conv == 2) ? w2 : w3;
    float v0 = w[(n*Cq + ci0    )*9 + tap];
    float v1 = w[(n*Cq + ci0 + 4)*9 + tap];
    uint32_t h0 = tf32_hi(v0), h1 = tf32_hi(v1);
    float l0 = v0 - __uint_as_float(h0);
    float l1 = v1 - __uint_as_float(h1);

    wB4[i] = make_float4(__uint_as_float(h0), __uint_as_float(h1), l0, l1);
}

// ---------------------------------------------------------------------------
// conv3x3 via mma.sync tf32x3, grouped by (dy, oct).
// CTA = one output row: D[128 px][64 co]. grid (Hq, 2*Bq), 8 warps.
// Warp tile 32x32: mw = wid&3, nw = wid>>2.
// A smem: [buf][px 0..129][20 floats], px = gx+1.
//   entry (px, c=k%4, h=k/4, plane) at px*20 + c*4 + h*2 + plane.
//   -> one LDS.128 at px*20 + c*4 gives (a0h, a0l, a2h, a2l).
// B smem: [buf][dx][nb][lane] float4 (bh0,bh1,bl0,bl1).
// ---------------------------------------------------------------------------
template<bool RELU_OUT>
__global__ __launch_bounds__(256, 2)
void conv_mma_kernel(const float* __restrict__ inA, const float* __restrict__ inB,
                     const float4* __restrict__ wBA, const float4* __restrict__ wBB,
                     const float* __restrict__ biasA, const float* __restrict__ biasB,
                     float* __restrict__ outA, float* __restrict__ outB)
{
    __shared__ alignas(16) float  sA[2][130*20];
    __shared__ float4 sB[2][768];

    const int y  = blockIdx.x;
    const int z  = blockIdx.y;
    const int b  = z & 3;
    const bool pB = (z >= 4);
    const float*  in   = (pB ? inB  : inA) + b*CHWq;
    const float4* wB   =  pB ? wBB  : wBA;
    const float*  bias =  pB ? biasB : biasA;
    float*        out  = (pB ? outB : outA) + b*CHWq;

    const int tid  = threadIdx.x;
    const int wid  = tid >> 5;
    const int lane = tid & 31;
    const int mw   = wid & 3;
    const int nw   = wid >> 2;

    const int sg  = tid >> 7;      // staging: k-half (h)
    const int spx = tid & 127;     // staging: gx

    // zero halo rows px=0 (gx=-1) and px=129 (gx=128), both buffers
    if (tid < 80) {
        int bb = tid / 40, rr = (tid / 20) & 1, cc = tid % 20;
        sA[bb][(rr ? 129*20 : 0) + cc] = 0.f;
    }

    float d[2][4][4];
#pragma unroll
    for (int mi = 0; mi < 2; mi++)
#pragma unroll
        for (int ni = 0; ni < 4; ni++)
#pragma unroll
            for (int r = 0; r < 4; r++) d[mi][ni][r] = 0.f;

    float v[4];
    auto preloadA = [&](int g) {
        int dy = g >> 3, oct = g & 7;
        int yin = y + dy - 1;
        bool ok = (yin >= 0) & (yin < Hq);
        const float* p = in + (oct*8 + sg*4)*HWq + yin*Wq + spx;
#pragma unroll
        for (int i = 0; i < 4; i++)
            v[i] = ok ? __ldg(p + i*HWq) : 0.f;
    };
    auto storeA = [&](int buf) {
#pragma unroll
        for (int i = 0; i < 4; i++) {
            uint32_t hi = tf32_hi(v[i]);
            float    lo = v[i] - __uint_as_float(hi);
            *(float2*)&sA[buf][(spx+1)*20 + i*4 + sg*2] =
                make_float2(__uint_as_float(hi), lo);
        }
    };
    auto stageB = [&](int buf, int g) {
        const float4* src = wB + g*768;
        cp16(&sB[buf][tid],       src + tid);
        cp16(&sB[buf][tid + 256], src + tid + 256);
        cp16(&sB[buf][tid + 512], src + tid + 512);
        CP_COMMIT;
    };

    preloadA(0);
    storeA(0);
    stageB(0, 0);

    for (int g = 0; g < NGRP; g++) {
        const int buf = g & 1;
        CP_WAIT0;
        __syncthreads();
        if (g + 1 < NGRP) { stageB(buf ^ 1, g + 1); preloadA(g + 1); }

#pragma unroll
        for (int dx = 0; dx < 3; dx++) {
            uint32_t ah[2][4], al[2][4];
#pragma unroll
            for (int mi = 0; mi < 2; mi++) {
                int pxl = mw*32 + mi*16 + (lane >> 2) + dx;
                float4 q0 = *(float4*)&sA[buf][pxl*20 + (lane & 3)*4];
                float4 q1 = *(float4*)&sA[buf][(pxl + 8)*20 + (lane & 3)*4];
                ah[mi][0] = __float_as_uint(q0.x); al[mi][0] = __float_as_uint(q0.y);
                ah[mi][2] = __float_as_uint(q0.z); al[mi][2] = __float_as_uint(q0.w);
                ah[mi][1] = __float_as_uint(q1.x); al[mi][1] = __float_as_uint(q1.y);
                ah[mi][3] = __float_as_uint(q1.z); al[mi][3] = __float_as_uint(q1.w);
            }
#pragma unroll
            for (int ni = 0; ni < 4; ni++) {
                float4 bq = sB[buf][(dx*8 + nw*4 + ni)*32 + lane];
                uint32_t bh0 = __float_as_uint(bq.x), bh1 = __float_as_uint(bq.y);
                uint32_t bl0 = __float_as_uint(bq.z), bl1 = __float_as_uint(bq.w);
#pragma unroll
                for (int mi = 0; mi < 2; mi++) {
                    mma_tf32(d[mi][ni], ah[mi], bh0, bh1);   // hi*hi
                    mma_tf32(d[mi][ni], al[mi], bh0, bh1);   // lo*hi
                    mma_tf32(d[mi][ni], ah[mi], bl0, bl1);   // hi*lo
                }
            }
        }

        if (g + 1 < NGRP) storeA(buf ^ 1);
        __syncthreads();
    }

    // epilogue: row = lane/4, col = 2*(lane%4)
    const int row  = lane >> 2;
    const int colb = (lane & 3) << 1;
    float* op = out + y*Wq;
#pragma unroll
    for (int mi = 0; mi < 2; mi++) {
        int px0 = mw*32 + mi*16 + row;
#pragma unroll
        for (int ni = 0; ni < 4; ni++) {
#pragma unroll
            for (int r = 0; r < 4; r++) {
                int co = nw*32 + ni*8 + colb + (r & 1);
                int px = px0 + ((r >> 1) << 3);
                float val = d[mi][ni][r] + __ldg(bias + co);
                if (RELU_OUT) val = fmaxf(val, 0.f);
                op[co*HWq + px] = val;
            }
        }
    }
}

// ---------------------------------------------------------------------------
// local_filter_path: conv1x1(64->64) -> relu -> conv1x1(64->49) -> normalize
// ---------------------------------------------------------------------------
__global__ __launch_bounds__(256, 1)
void lp_kernel(const float* __restrict__ kf,
               const float* __restrict__ w1, const float* __restrict__ b1,
               const float* __restrict__ w2, const float* __restrict__ b2,
               float* __restrict__ lp)
{
    __shared__ float s_w1[64*64];
    __shared__ float s_w2[64*52];
    __shared__ float s_b1[64];
    __shared__ float s_b2[49];
    const int tid = threadIdx.x;

    for (int i = tid; i < 64*64; i += 256) {
        int ci = i >> 6, co = i & 63;
        s_w1[i] = w1[co*64 + ci];
    }
    for (int i = tid; i < 64*49; i += 256) {
        int ci = i / 49, k = i - ci*49;
        s_w2[ci*52 + k] = w2[k*64 + ci];
    }
    if (tid < 64) s_b1[tid] = b1[tid];
    if (tid < 49) s_b2[tid] = b2[tid];
    __syncthreads();

    const int p  = blockIdx.x*256 + tid;
    const int b  = p >> 14;
    const int hw = p & (HWq-1);
    const float* kfp = kf + b*CHWq + hw;

    float h[64];
#pragma unroll
    for (int c = 0; c < 64; c++) h[c] = s_b1[c];
    for (int ci = 0; ci < 64; ci++) {
        float xv = kfp[ci*HWq];
#pragma unroll
        for (int co = 0; co < 64; co++)
            h[co] = fmaf(s_w1[ci*64 + co], xv, h[co]);
    }
#pragma unroll
    for (int c = 0; c < 64; c++) h[c] = fmaxf(h[c], 0.f);

    float o[TAPS];
#pragma unroll
    for (int k = 0; k < TAPS; k++) o[k] = s_b2[k];
    for (int ci = 0; ci < 64; ci++) {
        float hv = h[ci];
#pragma unroll
        for (int k = 0; k < TAPS; k++)
            o[k] = fmaf(s_w2[ci*52 + k], hv, o[k]);
    }
    float m = 0.f;
#pragma unroll
    for (int k = 0; k < TAPS; k++) m += o[k];
    m *= (1.0f/49.0f);

    float* lpp = lp + b*TAPS*HWq + hw;
#pragma unroll
    for (int k = 0; k < TAPS; k++)
        lpp[k*HWq] = o[k] - m + (1.0f/49.0f);
}

// ---------------------------------------------------------------------------
// dynamic 7x7 local conv + residual; feat = fp*mp computed on the fly.
// ---------------------------------------------------------------------------
#define TILE 16
#define LC_CG 8
#define LC_CPB (Cq/LC_CG)
__global__ __launch_bounds__(256, 2)
void local_conv_kernel(const float* __restrict__ x,
                       const float* __restrict__ fp, const float* __restrict__ mp,
                       const float* __restrict__ lp, float* __restrict__ out)
{
    __shared__ float s_f[22][24];
    const int bz = blockIdx.z;
    const int b  = bz >> 3;
    const int c0 = (bz & 7) * LC_CPB;
    const int x0 = blockIdx.x * TILE;
    const int y0 = blockIdx.y * TILE;
    const int tid = threadIdx.x;
    const int tx = tid & 15, ty = tid >> 4;
    const int y = y0 + ty, xx = x0 + tx;

    float kl[TAPS];
    const float* lpp = lp + b*TAPS*HWq + y*Wq + xx;
#pragma unroll
    for (int k = 0; k < TAPS; k++) kl[k] = lpp[k*HWq];

    const float* fpb = fp + b*CHWq;
    const float* mpb = mp + b*CHWq;
    const float* xb  = x  + b*CHWq;
    float*       ob  = out + b*CHWq;

    for (int ci = 0; ci < LC_CPB; ci++) {
        const int c = c0 + ci;
        __syncthreads();
        for (int i = tid; i < 22*22; i += 256) {
            int r  = i / 22;
            int cc = i - r*22;
            int gy = y0 + r - 3, gx = x0 + cc - 3;
            float v = 0.f;
            if (gy >= 0 && gy < Hq && gx >= 0 && gx < Wq) {
                int off = c*HWq + gy*Wq + gx;
                v = fpb[off] * mpb[off];
            }
            s_f[r][cc] = v;
        }
        __syncthreads();
        float acc = 0.f;
#pragma unroll
        for (int dy = 0; dy < KK; dy++)
#pragma unroll
            for (int dx = 0; dx < KK; dx++)
                acc = fmaf(s_f[ty+dy][tx+dx], kl[dy*KK+dx], acc);
        ob[c*HWq + y*Wq + xx] = xb[c*HWq + y*Wq + xx] + acc;
    }
}

// ---------------------------------------------------------------------------
extern "C" void kernel_launch(void* const* d_in, const int* in_sizes, int n_in,
                              void* d_out, int out_size)
{
    const float* x   = (const float*)d_in[0];
    const float* kf  = (const float*)d_in[1];
    const float* fw1 = (const float*)d_in[2];
    const float* fb1 = (const float*)d_in[3];
    const float* fw2 = (const float*)d_in[4];
    const float* fb2 = (const float*)d_in[5];
    const float* mw1 = (const float*)d_in[6];
    const float* mb1 = (const float*)d_in[7];
    const float* mw2 = (const float*)d_in[8];
    const float* mb2 = (const float*)d_in[9];
    const float* lw1 = (const float*)d_in[10];
    const float* lb1 = (const float*)d_in[11];
    const float* lw2 = (const float*)d_in[12];
    const float* lb2 = (const float*)d_in[13];
    float* out = (float*)d_out;

    float *rxp, *b1fp, *b1mp, *b2fp, *b2mp, *lpp;
    float4* wBp;
    cudaGetSymbolAddress((void**)&rxp,  g_rx);
    cudaGetSymbolAddress((void**)&b1fp, g_b1f);
    cudaGetSymbolAddress((void**)&b1mp, g_b1m);
    cudaGetSymbolAddress((void**)&b2fp, g_b2f);
    cudaGetSymbolAddress((void**)&b2mp, g_b2m);
    cudaGetSymbolAddress((void**)&lpp,  g_lp);
    cudaGetSymbolAddress((void**)&wBp,  g_wB4);

    dim3 cblk(256);
    prep_relu_kernel<<<(Bq*CHWq/4)/256, cblk>>>(x, rxp);
    prep_wt_kernel<<<(4*WB4_CONV)/256, cblk>>>(fw1, fw2, mw1, mw2, wBp);
    lp_kernel<<<(Bq*HWq)/256, cblk>>>(kf, lw1, lb1, lw2, lb2, lpp);

    dim3 tgrid(Hq, 2*Bq);   // 1024 CTAs per stage
    const float4* wf1 = wBp + 0*WB4_CONV;
    const float4* wf2 = wBp + 1*WB4_CONV;
    const float4* wm1 = wBp + 2*WB4_CONV;
    const float4* wm2 = wBp + 3*WB4_CONV;

    conv_mma_kernel<true><<<tgrid, cblk>>>(
        rxp, kf, wf1, wm1, fb1, mb1, b1fp, b1mp);
    conv_mma_kernel<false><<<tgrid, cblk>>>(
        b1fp, b1mp, wf2, wm2, fb2, mb2, b2fp, b2mp);

    dim3 lgrid(Wq/TILE, Hq/TILE, Bq*LC_CG);
    local_conv_kernel<<<lgrid, cblk>>>(x, b2fp, b2mp, lpp, out);
}

// round 9
// speedup vs baseline: 1.4465x; 1.2680x over previous
#include <cuda_runtime.h>
#include <cstdint>

#define Bq 4
#define Cq 64
#define Hq 128
#define Wq 128
#define HWq (Hq*Wq)
#define CHWq (Cq*HWq)
#define KK 7
#define TAPS 49
#define NGRP 24                 // (dy 3) x (oct 8)
#define NKB  72                 // NGRP * 3 dx
#define WB2_CONV (NKB*256)      // float2 per conv: 72 kb * 8 nb * 32 lane

// scratch (allocation-free rule: __device__ globals)
__device__ float  g_rx [Bq*CHWq];
__device__ float  g_b1f[Bq*CHWq];
__device__ float  g_b1m[Bq*CHWq];
__device__ float  g_b2f[Bq*CHWq];
__device__ float  g_b2m[Bq*CHWq];
__device__ float  g_ft [Bq*CHWq];      // feat = fp*mp
__device__ float  g_lp [Bq*TAPS*HWq];
__device__ float2 g_wB2[4*WB2_CONV];   // packed B frags (b0_hi, b1_hi)

// ---------------------------------------------------------------------------
__device__ __forceinline__ uint32_t tf32_hi(float v) {
    uint32_t r; asm("cvt.rna.tf32.f32 %0, %1;" : "=r"(r) : "f"(v)); return r;
}
__device__ __forceinline__ void cp16(void* dst, const void* src) {
    unsigned d = (unsigned)__cvta_generic_to_shared(dst);
    asm volatile("cp.async.ca.shared.global [%0], [%1], 16;" :: "r"(d), "l"(src));
}
__device__ __forceinline__ void cp4z(void* dst, const void* src, unsigned sz) {
    unsigned d = (unsigned)__cvta_generic_to_shared(dst);
    asm volatile("cp.async.ca.shared.global [%0], [%1], 4, %2;" :: "r"(d), "l"(src), "r"(sz));
}
#define CP_COMMIT asm volatile("cp.async.commit_group;")
#define CP_WAIT0  asm volatile("cp.async.wait_group 0;")

__device__ __forceinline__ void mma_tf32(float d[4], const uint32_t a[4],
                                         uint32_t b0, uint32_t b1)
{
    asm volatile(
        "mma.sync.aligned.m16n8k8.row.col.f32.tf32.tf32.f32 "
        "{%0,%1,%2,%3}, {%4,%5,%6,%7}, {%8,%9}, {%0,%1,%2,%3};"
        : "+f"(d[0]), "+f"(d[1]), "+f"(d[2]), "+f"(d[3])
        : "r"(a[0]), "r"(a[1]), "r"(a[2]), "r"(a[3]), "r"(b0), "r"(b1));
}

// ---------------------------------------------------------------------------
// prep kernels
// ---------------------------------------------------------------------------
__global__ void prep_relu_kernel(const float* __restrict__ x, float* __restrict__ rx)
{
    int i = blockIdx.x*256 + threadIdx.x;
    float4 v = ((const float4*)x)[i];
    v.x = fmaxf(v.x, 0.f); v.y = fmaxf(v.y, 0.f);
    v.z = fmaxf(v.z, 0.f); v.w = fmaxf(v.w, 0.f);
    ((float4*)rx)[i] = v;
}
__global__ void prep_mul_kernel(const float* __restrict__ a, const float* __restrict__ b,
                                float* __restrict__ o)
{
    int i = blockIdx.x*256 + threadIdx.x;
    float4 va = ((const float4*)a)[i];
    float4 vb = ((const float4*)b)[i];
    ((float4*)o)[i] = make_float4(va.x*vb.x, va.y*vb.y, va.z*vb.z, va.w*vb.w);
}

// Pack weights: kb = (dy*8+oct)*3 + dx, tap = dy*3+dx.
// frag: b0 = B[k=lane%4][n], b1 = B[k+4][n]; ci = oct*8 + k. hi plane only.
__global__ void prep_wt_kernel(const float* __restrict__ w0, const float* __restrict__ w1,
                               const float* __restrict__ w2, const float* __restrict__ w3,
                               float2* __restrict__ wB2)
{
    int i = blockIdx.x*256 + threadIdx.x;    // 0 .. 4*72*256-1
    int conv = i / WB2_CONV;
    int r    = i - conv*WB2_CONV;
    int kb   = r >> 8;
    int r2   = r & 255;
    int nb   = r2 >> 5;
    int lane = r2 & 31;

    int g  = kb / 3, dx = kb - g*3;
    int dy = g >> 3, oct = g & 7;
    int tap = dy*3 + dx;
    int n   = nb*8 + (lane >> 2);
    int ci0 = oct*8 + (lane & 3);

    const float* w = (conv == 0) ? w0 : (conv == 1) ? w1 : (conv == 2) ? w2 : w3;
    float v0 = w[(n*Cq + ci0    )*9 + tap];
    float v1 = w[(n*Cq + ci0 + 4)*9 + tap];
    wB2[i] = make_float2(__uint_as_float(tf32_hi(v0)), __uint_as_float(tf32_hi(v1)));
}

// ---------------------------------------------------------------------------
// conv3x3 via mma.sync tf32x2 (hh + lh), grouped by (dy, oct).
// CTA = one output row: D[128 px][64 co]. grid (Hq, 2*Bq), 8 warps.
// Warp tile 32x32: mw = wid&3, nw = wid>>2.
// A smem: [buf][px 0..129][20], entry (px,c) float4 = (hi_k=c, lo_k=c,
//   hi_k=c+4, lo_k=c+4) at px*20 + c*4. Staged by 128 threads (1 px each,
//   8 LDG + 4 STS.128). B smem: hi-only float2 frags (6KB/buf) via cp.async.
// ---------------------------------------------------------------------------
template<bool RELU_OUT>
__global__ __launch_bounds__(256, 2)
void conv_mma_kernel(const float* __restrict__ inA, const float* __restrict__ inB,
                     const float2* __restrict__ wBA, const float2* __restrict__ wBB,
                     const float* __restrict__ biasA, const float* __restrict__ biasB,
                     float* __restrict__ outA, float* __restrict__ outB)
{
    __shared__ alignas(16) float  sA[2][130*20];
    __shared__ alignas(16) float2 sB[2][768];

    const int y  = blockIdx.x;
    const int z  = blockIdx.y;
    const int b  = z & 3;
    const bool pB = (z >= 4);
    const float*  in   = (pB ? inB  : inA) + b*CHWq;
    const float2* wB   =  pB ? wBB  : wBA;
    const float*  bias =  pB ? biasB : biasA;
    float*        out  = (pB ? outB : outA) + b*CHWq;

    const int tid  = threadIdx.x;
    const int wid  = tid >> 5;
    const int lane = tid & 31;
    const int mw   = wid & 3;
    const int nw   = wid >> 2;

    // zero halo rows px=0 (gx=-1) and px=129 (gx=128), both buffers
    if (tid < 80) {
        int bb = tid / 40, rr = (tid / 20) & 1, cc = tid % 20;
        sA[bb][(rr ? 129*20 : 0) + cc] = 0.f;
    }

    float d[2][4][4];
#pragma unroll
    for (int mi = 0; mi < 2; mi++)
#pragma unroll
        for (int ni = 0; ni < 4; ni++)
#pragma unroll
            for (int r = 0; r < 4; r++) d[mi][ni][r] = 0.f;

    // A staging: threads 0..127, one px each, 8 ci values
    float v[8];
    auto preloadA = [&](int g) {
        if (tid < 128) {
            int dy = g >> 3, oct = g & 7;
            int yin = y + dy - 1;
            bool ok = (yin >= 0) & (yin < Hq);
            const float* p = in + oct*8*HWq + yin*Wq + tid;
#pragma unroll
            for (int i = 0; i < 8; i++)
                v[i] = ok ? __ldg(p + i*HWq) : 0.f;
        }
    };
    auto storeA = [&](int buf) {
        if (tid < 128) {
#pragma unroll
            for (int c = 0; c < 4; c++) {
                uint32_t h0 = tf32_hi(v[c]);
                uint32_t h1 = tf32_hi(v[c+4]);
                float l0 = v[c]   - __uint_as_float(h0);
                float l1 = v[c+4] - __uint_as_float(h1);
                *(float4*)&sA[buf][(tid+1)*20 + c*4] =
                    make_float4(__uint_as_float(h0), l0, __uint_as_float(h1), l1);
            }
        }
    };
    auto stageB = [&](int buf, int g) {
        const float4* src = (const float4*)(wB + g*768);   // 384 x 16B
        float4* dst = (float4*)sB[buf];
        cp16(dst + tid, src + tid);
        if (tid < 128) cp16(dst + 256 + tid, src + 256 + tid);
        CP_COMMIT;
    };

    preloadA(0);
    storeA(0);
    stageB(0, 0);

    for (int g = 0; g < NGRP; g++) {
        const int buf = g & 1;
        CP_WAIT0;
        __syncthreads();
        if (g + 1 < NGRP) { stageB(buf ^ 1, g + 1); preloadA(g + 1); }

#pragma unroll
        for (int dx = 0; dx < 3; dx++) {
            uint32_t ah[2][4], al[2][4];
#pragma unroll
            for (int mi = 0; mi < 2; mi++) {
                int pxl = mw*32 + mi*16 + (lane >> 2) + dx;
                float4 q0 = *(float4*)&sA[buf][pxl*20 + (lane & 3)*4];
                float4 q1 = *(float4*)&sA[buf][(pxl + 8)*20 + (lane & 3)*4];
                ah[mi][0] = __float_as_uint(q0.x); al[mi][0] = __float_as_uint(q0.y);
                ah[mi][2] = __float_as_uint(q0.z); al[mi][2] = __float_as_uint(q0.w);
                ah[mi][1] = __float_as_uint(q1.x); al[mi][1] = __float_as_uint(q1.y);
                ah[mi][3] = __float_as_uint(q1.z); al[mi][3] = __float_as_uint(q1.w);
            }
#pragma unroll
            for (int ni = 0; ni < 4; ni++) {
                float2 bq = sB[buf][(dx*8 + nw*4 + ni)*32 + lane];
                uint32_t b0 = __float_as_uint(bq.x), b1 = __float_as_uint(bq.y);
#pragma unroll
                for (int mi = 0; mi < 2; mi++) {
                    mma_tf32(d[mi][ni], ah[mi], b0, b1);   // hi*hi
                    mma_tf32(d[mi][ni], al[mi], b0, b1);   // lo*hi
                }
            }
        }

        if (g + 1 < NGRP) storeA(buf ^ 1);
        __syncthreads();
    }

    // epilogue: row = lane/4, col = 2*(lane%4)
    const int row  = lane >> 2;
    const int colb = (lane & 3) << 1;
    float* op = out + y*Wq;
#pragma unroll
    for (int mi = 0; mi < 2; mi++) {
        int px0 = mw*32 + mi*16 + row;
#pragma unroll
        for (int ni = 0; ni < 4; ni++) {
#pragma unroll
            for (int r = 0; r < 4; r++) {
                int co = nw*32 + ni*8 + colb + (r & 1);
                int px = px0 + ((r >> 1) << 3);
                float val = d[mi][ni][r] + __ldg(bias + co);
                if (RELU_OUT) val = fmaxf(val, 0.f);
                op[co*HWq + px] = val;
            }
        }
    }
}

// ---------------------------------------------------------------------------
// local_filter_path: conv1x1(64->64) -> relu -> conv1x1(64->49) -> normalize
// ---------------------------------------------------------------------------
__global__ __launch_bounds__(256, 1)
void lp_kernel(const float* __restrict__ kf,
               const float* __restrict__ w1, const float* __restrict__ b1,
               const float* __restrict__ w2, const float* __restrict__ b2,
               float* __restrict__ lp)
{
    __shared__ float s_w1[64*64];
    __shared__ float s_w2[64*52];
    __shared__ float s_b1[64];
    __shared__ float s_b2[49];
    const int tid = threadIdx.x;

    for (int i = tid; i < 64*64; i += 256) {
        int ci = i >> 6, co = i & 63;
        s_w1[i] = w1[co*64 + ci];
    }
    for (int i = tid; i < 64*49; i += 256) {
        int ci = i / 49, k = i - ci*49;
        s_w2[ci*52 + k] = w2[k*64 + ci];
    }
    if (tid < 64) s_b1[tid] = b1[tid];
    if (tid < 49) s_b2[tid] = b2[tid];
    __syncthreads();

    const int p  = blockIdx.x*256 + tid;
    const int b  = p >> 14;
    const int hw = p & (HWq-1);
    const float* kfp = kf + b*CHWq + hw;

    float h[64];
#pragma unroll
    for (int c = 0; c < 64; c++) h[c] = s_b1[c];
    for (int ci = 0; ci < 64; ci++) {
        float xv = kfp[ci*HWq];
#pragma unroll
        for (int co = 0; co < 64; co++)
            h[co] = fmaf(s_w1[ci*64 + co], xv, h[co]);
    }
#pragma unroll
    for (int c = 0; c < 64; c++) h[c] = fmaxf(h[c], 0.f);

    float o[TAPS];
#pragma unroll
    for (int k = 0; k < TAPS; k++) o[k] = s_b2[k];
    for (int ci = 0; ci < 64; ci++) {
        float hv = h[ci];
#pragma unroll
        for (int k = 0; k < TAPS; k++)
            o[k] = fmaf(s_w2[ci*52 + k], hv, o[k]);
    }
    float m = 0.f;
#pragma unroll
    for (int k = 0; k < TAPS; k++) m += o[k];
    m *= (1.0f/49.0f);

    float* lpp = lp + b*TAPS*HWq + hw;
#pragma unroll
    for (int k = 0; k < TAPS; k++)
        lpp[k*HWq] = o[k] - m + (1.0f/49.0f);
}

// ---------------------------------------------------------------------------
// dynamic 7x7 local conv + residual; feat pre-multiplied. cp.async
// double-buffered tile staging, 1 sync per channel.
// ---------------------------------------------------------------------------
#define TILE 16
#define LC_CG 8
#define LC_CPB (Cq/LC_CG)
__global__ __launch_bounds__(256, 2)
void local_conv_kernel(const float* __restrict__ x, const float* __restrict__ feat,
                       const float* __restrict__ lp, float* __restrict__ out)
{
    __shared__ float s_f[2][22][24];
    const int bz = blockIdx.z;
    const int b  = bz >> 3;
    const int c0 = (bz & 7) * LC_CPB;
    const int x0 = blockIdx.x * TILE;
    const int y0 = blockIdx.y * TILE;
    const int tid = threadIdx.x;
    const int tx = tid & 15, ty = tid >> 4;
    const int y = y0 + ty, xx = x0 + tx;

    float kl[TAPS];
    const float* lpp = lp + b*TAPS*HWq + y*Wq + xx;
#pragma unroll
    for (int k = 0; k < TAPS; k++) kl[k] = lpp[k*HWq];

    const float* fb = feat + b*CHWq;
    const float* xb = x    + b*CHWq;
    float*       ob = out  + b*CHWq;

    auto stageF = [&](int buf, int c) {
        for (int i = tid; i < 22*22; i += 256) {
            int r  = i / 22;
            int cc = i - r*22;
            int gy = y0 + r - 3, gx = x0 + cc - 3;
            bool ok = (gy >= 0) & (gy < Hq) & (gx >= 0) & (gx < Wq);
            const float* src = ok ? (fb + c*HWq + gy*Wq + gx) : fb;
            cp4z(&s_f[buf][r][cc], src, ok ? 4u : 0u);
        }
        CP_COMMIT;
    };

    stageF(0, c0);
    for (int ci = 0; ci < LC_CPB; ci++) {
        const int c = c0 + ci;
        const int buf = ci & 1;
        CP_WAIT0;
        __syncthreads();
        if (ci + 1 < LC_CPB) stageF(buf ^ 1, c + 1);
        float acc = 0.f;
#pragma unroll
        for (int dy = 0; dy < KK; dy++)
#pragma unroll
            for (int dx = 0; dx < KK; dx++)
                acc = fmaf(s_f[buf][ty+dy][tx+dx], kl[dy*KK+dx], acc);
        ob[c*HWq + y*Wq + xx] = xb[c*HWq + y*Wq + xx] + acc;
    }
}

// ---------------------------------------------------------------------------
extern "C" void kernel_launch(void* const* d_in, const int* in_sizes, int n_in,
                              void* d_out, int out_size)
{
    const float* x   = (const float*)d_in[0];
    const float* kf  = (const float*)d_in[1];
    const float* fw1 = (const float*)d_in[2];
    const float* fb1 = (const float*)d_in[3];
    const float* fw2 = (const float*)d_in[4];
    const float* fb2 = (const float*)d_in[5];
    const float* mw1 = (const float*)d_in[6];
    const float* mb1 = (const float*)d_in[7];
    const float* mw2 = (const float*)d_in[8];
    const float* mb2 = (const float*)d_in[9];
    const float* lw1 = (const float*)d_in[10];
    const float* lb1 = (const float*)d_in[11];
    const float* lw2 = (const float*)d_in[12];
    const float* lb2 = (const float*)d_in[13];
    float* out = (float*)d_out;

    float *rxp, *b1fp, *b1mp, *b2fp, *b2mp, *ftp, *lpp;
    float2* wBp;
    cudaGetSymbolAddress((void**)&rxp,  g_rx);
    cudaGetSymbolAddress((void**)&b1fp, g_b1f);
    cudaGetSymbolAddress((void**)&b1mp, g_b1m);
    cudaGetSymbolAddress((void**)&b2fp, g_b2f);
    cudaGetSymbolAddress((void**)&b2mp, g_b2m);
    cudaGetSymbolAddress((void**)&ftp,  g_ft);
    cudaGetSymbolAddress((void**)&lpp,  g_lp);
    cudaGetSymbolAddress((void**)&wBp,  g_wB2);

    dim3 cblk(256);
    prep_relu_kernel<<<(Bq*CHWq/4)/256, cblk>>>(x, rxp);
    prep_wt_kernel<<<(4*WB2_CONV)/256, cblk>>>(fw1, fw2, mw1, mw2, wBp);
    lp_kernel<<<(Bq*HWq)/256, cblk>>>(kf, lw1, lb1, lw2, lb2, lpp);

    dim3 tgrid(Hq, 2*Bq);   // 1024 CTAs per stage
    const float2* wf1 = wBp + 0*WB2_CONV;
    const float2* wf2 = wBp + 1*WB2_CONV;
    const float2* wm1 = wBp + 2*WB2_CONV;
    const float2* wm2 = wBp + 3*WB2_CONV;

    conv_mma_kernel<true><<<tgrid, cblk>>>(
        rxp, kf, wf1, wm1, fb1, mb1, b1fp, b1mp);
    conv_mma_kernel<false><<<tgrid, cblk>>>(
        b1fp, b1mp, wf2, wm2, fb2, mb2, b2fp, b2mp);

    // feat = fp * mp
    prep_mul_kernel<<<(Bq*CHWq/4)/256, cblk>>>(b2fp, b2mp, ftp);

    dim3 lgrid(Wq/TILE, Hq/TILE, Bq*LC_CG);
    local_conv_kernel<<<lgrid, cblk>>>(x, ftp, lpp, out);
}

// round 10
// speedup vs baseline: 2.0055x; 1.3864x over previous
#include <cuda_runtime.h>
#include <cstdint>

#define Bq 4
#define Cq 64
#define Hq 128
#define Wq 128
#define HWq (Hq*Wq)
#define CHWq (Cq*HWq)
#define KK 7
#define TAPS 49
#define NGRP 24                 // (dy 3) x (oct 8)
#define NKB  72                 // NGRP * 3 dx
#define WB2_CONV (NKB*256)      // float2 per conv: 72 kb * 8 nb * 32 lane

// scratch (allocation-free rule: __device__ globals)
__device__ float  g_rx [Bq*CHWq];
__device__ float  g_b1f[Bq*CHWq];
__device__ float  g_b1m[Bq*CHWq];
__device__ float  g_b2f[Bq*CHWq];
__device__ float  g_b2m[Bq*CHWq];
__device__ float  g_ft [Bq*CHWq];      // feat = fp*mp
__device__ float  g_lp [Bq*TAPS*HWq];
__device__ float2 g_wB2[4*WB2_CONV];   // packed B frags (b0_hi, b1_hi)

// ---------------------------------------------------------------------------
__device__ __forceinline__ uint32_t tf32_hi(float v) {
    uint32_t r; asm("cvt.rna.tf32.f32 %0, %1;" : "=r"(r) : "f"(v)); return r;
}
__device__ __forceinline__ void cp16(void* dst, const void* src) {
    unsigned d = (unsigned)__cvta_generic_to_shared(dst);
    asm volatile("cp.async.ca.shared.global [%0], [%1], 16;" :: "r"(d), "l"(src));
}
__device__ __forceinline__ void cp4z(void* dst, const void* src, unsigned sz) {
    unsigned d = (unsigned)__cvta_generic_to_shared(dst);
    asm volatile("cp.async.ca.shared.global [%0], [%1], 4, %2;" :: "r"(d), "l"(src), "r"(sz));
}
#define CP_COMMIT asm volatile("cp.async.commit_group;")
#define CP_WAIT0  asm volatile("cp.async.wait_group 0;")

__device__ __forceinline__ void mma_tf32(float d[4], const uint32_t a[4],
                                         uint32_t b0, uint32_t b1)
{
    asm volatile(
        "mma.sync.aligned.m16n8k8.row.col.f32.tf32.tf32.f32 "
        "{%0,%1,%2,%3}, {%4,%5,%6,%7}, {%8,%9}, {%0,%1,%2,%3};"
        : "+f"(d[0]), "+f"(d[1]), "+f"(d[2]), "+f"(d[3])
        : "r"(a[0]), "r"(a[1]), "r"(a[2]), "r"(a[3]), "r"(b0), "r"(b1));
}

// ---------------------------------------------------------------------------
// prep kernels
// ---------------------------------------------------------------------------
__global__ void prep_relu_kernel(const float* __restrict__ x, float* __restrict__ rx)
{
    int i = blockIdx.x*256 + threadIdx.x;
    float4 v = ((const float4*)x)[i];
    v.x = fmaxf(v.x, 0.f); v.y = fmaxf(v.y, 0.f);
    v.z = fmaxf(v.z, 0.f); v.w = fmaxf(v.w, 0.f);
    ((float4*)rx)[i] = v;
}
__global__ void prep_mul_kernel(const float* __restrict__ a, const float* __restrict__ b,
                                float* __restrict__ o)
{
    int i = blockIdx.x*256 + threadIdx.x;
    float4 va = ((const float4*)a)[i];
    float4 vb = ((const float4*)b)[i];
    ((float4*)o)[i] = make_float4(va.x*vb.x, va.y*vb.y, va.z*vb.z, va.w*vb.w);
}

// Pack weights: kb = (dy*8+oct)*3 + dx, tap = dy*3+dx.
// frag: b0 = B[k=lane%4][n], b1 = B[k+4][n]; ci = oct*8 + k. hi plane only.
__global__ void prep_wt_kernel(const float* __restrict__ w0, const float* __restrict__ w1,
                               const float* __restrict__ w2, const float* __restrict__ w3,
                               float2* __restrict__ wB2)
{
    int i = blockIdx.x*256 + threadIdx.x;    // 0 .. 4*72*256-1
    int conv = i / WB2_CONV;
    int r    = i - conv*WB2_CONV;
    int kb   = r >> 8;
    int r2   = r & 255;
    int nb   = r2 >> 5;
    int lane = r2 & 31;

    int g  = kb / 3, dx = kb - g*3;
    int dy = g >> 3, oct = g & 7;
    int tap = dy*3 + dx;
    int n   = nb*8 + (lane >> 2);
    int ci0 = oct*8 + (lane & 3);

    const float* w = (conv == 0) ? w0 : (conv == 1) ? w1 : (conv == 2) ? w2 : w3;
    float v0 = w[(n*Cq + ci0    )*9 + tap];
    float v1 = w[(n*Cq + ci0 + 4)*9 + tap];
    wB2[i] = make_float2(__uint_as_float(tf32_hi(v0)), __uint_as_float(tf32_hi(v1)));
}

// ---------------------------------------------------------------------------
// conv3x3 via mma.sync tf32 1-pass (hi*hi), grouped by (dy, oct).
// CTA = one output row: D[128 px][64 co]. grid (Hq, 2*Bq), 8 warps.
// Warp tile 32x32: mw = wid&3, nw = wid>>2.
// A smem: [buf][px 0..129][8 floats], stride 8 (32B), conflict-free:
//   logical float2 (v_c, v_{c+4}) at pair p=c>>1 stored at
//   px*8 + ((p ^ ((px>>2)&1))<<2) + (c&1)*2.
// B smem: hi-only float2 frags via cp.async.
// ---------------------------------------------------------------------------
template<bool RELU_OUT>
__global__ __launch_bounds__(256, 3)
void conv_mma_kernel(const float* __restrict__ inA, const float* __restrict__ inB,
                     const float2* __restrict__ wBA, const float2* __restrict__ wBB,
                     const float* __restrict__ biasA, const float* __restrict__ biasB,
                     float* __restrict__ outA, float* __restrict__ outB)
{
    __shared__ alignas(16) float  sA[2][130*8];
    __shared__ alignas(16) float2 sB[2][768];

    const int y  = blockIdx.x;
    const int z  = blockIdx.y;
    const int b  = z & 3;
    const bool pB = (z >= 4);
    const float*  in   = (pB ? inB  : inA) + b*CHWq;
    const float2* wB   =  pB ? wBB  : wBA;
    const float*  bias =  pB ? biasB : biasA;
    float*        out  = (pB ? outB : outA) + b*CHWq;

    const int tid  = threadIdx.x;
    const int wid  = tid >> 5;
    const int lane = tid & 31;
    const int mw   = wid & 3;
    const int nw   = wid >> 2;

    // zero halo rows px=0 (gx=-1) and px=129 (gx=128), both buffers
    if (tid < 32) {
        int bb = tid >> 4, rr = (tid >> 3) & 1, cc = tid & 7;
        sA[bb][(rr ? 129*8 : 0) + cc] = 0.f;
    }

    float d[2][4][4];
#pragma unroll
    for (int mi = 0; mi < 2; mi++)
#pragma unroll
        for (int ni = 0; ni < 4; ni++)
#pragma unroll
            for (int r = 0; r < 4; r++) d[mi][ni][r] = 0.f;

    // A staging: threads 0..127, one px each, 8 ci values
    float v[8];
    auto preloadA = [&](int g) {
        if (tid < 128) {
            int dy = g >> 3, oct = g & 7;
            int yin = y + dy - 1;
            bool ok = (yin >= 0) & (yin < Hq);
            const float* p = in + oct*8*HWq + yin*Wq + tid;
#pragma unroll
            for (int i = 0; i < 8; i++)
                v[i] = ok ? __ldg(p + i*HWq) : 0.f;
        }
    };
    auto storeA = [&](int buf) {
        if (tid < 128) {
            int px = tid + 1;
            int sw = (px >> 2) & 1;
            float* base = &sA[buf][px*8];
            float4 p0 = make_float4(__uint_as_float(tf32_hi(v[0])),
                                    __uint_as_float(tf32_hi(v[4])),
                                    __uint_as_float(tf32_hi(v[1])),
                                    __uint_as_float(tf32_hi(v[5])));
            float4 p1 = make_float4(__uint_as_float(tf32_hi(v[2])),
                                    __uint_as_float(tf32_hi(v[6])),
                                    __uint_as_float(tf32_hi(v[3])),
                                    __uint_as_float(tf32_hi(v[7])));
            *(float4*)(base + ((0 ^ sw) << 2)) = p0;
            *(float4*)(base + ((1 ^ sw) << 2)) = p1;
        }
    };
    auto stageB = [&](int buf, int g) {
        const float4* src = (const float4*)(wB + g*768);   // 384 x 16B
        float4* dst = (float4*)sB[buf];
        cp16(dst + tid, src + tid);
        if (tid < 128) cp16(dst + 256 + tid, src + 256 + tid);
        CP_COMMIT;
    };

    preloadA(0);
    storeA(0);
    stageB(0, 0);

    for (int g = 0; g < NGRP; g++) {
        const int buf = g & 1;
        CP_WAIT0;
        __syncthreads();
        if (g + 1 < NGRP) { stageB(buf ^ 1, g + 1); preloadA(g + 1); }

#pragma unroll
        for (int dx = 0; dx < 3; dx++) {
            uint32_t a[2][4];
#pragma unroll
            for (int mi = 0; mi < 2; mi++) {
                int pxl = mw*32 + mi*16 + (lane >> 2) + dx;
                int c   = lane & 3;
                int sw  = (pxl >> 2) & 1;   // same parity for pxl and pxl+8
                int off = (((c >> 1) ^ sw) << 2) + ((c & 1) << 1);
                float2 q0 = *(float2*)&sA[buf][pxl*8 + off];
                float2 q1 = *(float2*)&sA[buf][(pxl + 8)*8 + off];
                a[mi][0] = __float_as_uint(q0.x);
                a[mi][2] = __float_as_uint(q0.y);
                a[mi][1] = __float_as_uint(q1.x);
                a[mi][3] = __float_as_uint(q1.y);
            }
#pragma unroll
            for (int ni = 0; ni < 4; ni++) {
                float2 bq = sB[buf][(dx*8 + nw*4 + ni)*32 + lane];
                uint32_t b0 = __float_as_uint(bq.x), b1 = __float_as_uint(bq.y);
#pragma unroll
                for (int mi = 0; mi < 2; mi++)
                    mma_tf32(d[mi][ni], a[mi], b0, b1);
            }
        }

        if (g + 1 < NGRP) storeA(buf ^ 1);
        __syncthreads();
    }

    // epilogue: row = lane/4, col = 2*(lane%4)
    const int row  = lane >> 2;
    const int colb = (lane & 3) << 1;
    float* op = out + y*Wq;
#pragma unroll
    for (int mi = 0; mi < 2; mi++) {
        int px0 = mw*32 + mi*16 + row;
#pragma unroll
        for (int ni = 0; ni < 4; ni++) {
#pragma unroll
            for (int r = 0; r < 4; r++) {
                int co = nw*32 + ni*8 + colb + (r & 1);
                int px = px0 + ((r >> 1) << 3);
                float val = d[mi][ni][r] + __ldg(bias + co);
                if (RELU_OUT) val = fmaxf(val, 0.f);
                op[co*HWq + px] = val;
            }
        }
    }
}

// ---------------------------------------------------------------------------
// local_filter_path: conv1x1(64->64) -> relu -> conv1x1(64->49) -> normalize
// ---------------------------------------------------------------------------
__global__ __launch_bounds__(256, 1)
void lp_kernel(const float* __restrict__ kf,
               const float* __restrict__ w1, const float* __restrict__ b1,
               const float* __restrict__ w2, const float* __restrict__ b2,
               float* __restrict__ lp)
{
    __shared__ float s_w1[64*64];
    __shared__ float s_w2[64*52];
    __shared__ float s_b1[64];
    __shared__ float s_b2[49];
    const int tid = threadIdx.x;

    for (int i = tid; i < 64*64; i += 256) {
        int ci = i >> 6, co = i & 63;
        s_w1[i] = w1[co*64 + ci];
    }
    for (int i = tid; i < 64*49; i += 256) {
        int ci = i / 49, k = i - ci*49;
        s_w2[ci*52 + k] = w2[k*64 + ci];
    }
    if (tid < 64) s_b1[tid] = b1[tid];
    if (tid < 49) s_b2[tid] = b2[tid];
    __syncthreads();

    const int p  = blockIdx.x*256 + tid;
    const int b  = p >> 14;
    const int hw = p & (HWq-1);
    const float* kfp = kf + b*CHWq + hw;

    float h[64];
#pragma unroll
    for (int c = 0; c < 64; c++) h[c] = s_b1[c];
    for (int ci = 0; ci < 64; ci++) {
        float xv = kfp[ci*HWq];
#pragma unroll
        for (int co = 0; co < 64; co++)
            h[co] = fmaf(s_w1[ci*64 + co], xv, h[co]);
    }
#pragma unroll
    for (int c = 0; c < 64; c++) h[c] = fmaxf(h[c], 0.f);

    float o[TAPS];
#pragma unroll
    for (int k = 0; k < TAPS; k++) o[k] = s_b2[k];
    for (int ci = 0; ci < 64; ci++) {
        float hv = h[ci];
#pragma unroll
        for (int k = 0; k < TAPS; k++)
            o[k] = fmaf(s_w2[ci*52 + k], hv, o[k]);
    }
    float m = 0.f;
#pragma unroll
    for (int k = 0; k < TAPS; k++) m += o[k];
    m *= (1.0f/49.0f);

    float* lpp = lp + b*TAPS*HWq + hw;
#pragma unroll
    for (int k = 0; k < TAPS; k++)
        lpp[k*HWq] = o[k] - m + (1.0f/49.0f);
}

// ---------------------------------------------------------------------------
// dynamic 7x7 local conv + residual; feat pre-multiplied. cp.async
// double-buffered tile staging, 1 sync per channel.
// ---------------------------------------------------------------------------
#define TILE 16
#define LC_CG 8
#define LC_CPB (Cq/LC_CG)
__global__ __launch_bounds__(256, 2)
void local_conv_kernel(const float* __restrict__ x, const float* __restrict__ feat,
                       const float* __restrict__ lp, float* __restrict__ out)
{
    __shared__ float s_f[2][22][24];
    const int bz = blockIdx.z;
    const int b  = bz >> 3;
    const int c0 = (bz & 7) * LC_CPB;
    const int x0 = blockIdx.x * TILE;
    const int y0 = blockIdx.y * TILE;
    const int tid = threadIdx.x;
    const int tx = tid & 15, ty = tid >> 4;
    const int y = y0 + ty, xx = x0 + tx;

    float kl[TAPS];
    const float* lpp = lp + b*TAPS*HWq + y*Wq + xx;
#pragma unroll
    for (int k = 0; k < TAPS; k++) kl[k] = lpp[k*HWq];

    const float* fb = feat + b*CHWq;
    const float* xb = x    + b*CHWq;
    float*       ob = out  + b*CHWq;

    auto stageF = [&](int buf, int c) {
        for (int i = tid; i < 22*22; i += 256) {
            int r  = i / 22;
            int cc = i - r*22;
            int gy = y0 + r - 3, gx = x0 + cc - 3;
            bool ok = (gy >= 0) & (gy < Hq) & (gx >= 0) & (gx < Wq);
            const float* src = ok ? (fb + c*HWq + gy*Wq + gx) : fb;
            cp4z(&s_f[buf][r][cc], src, ok ? 4u : 0u);
        }
        CP_COMMIT;
    };

    stageF(0, c0);
    for (int ci = 0; ci < LC_CPB; ci++) {
        const int c = c0 + ci;
        const int buf = ci & 1;
        CP_WAIT0;
        __syncthreads();
        if (ci + 1 < LC_CPB) stageF(buf ^ 1, c + 1);
        float acc = 0.f;
#pragma unroll
        for (int dy = 0; dy < KK; dy++)
#pragma unroll
            for (int dx = 0; dx < KK; dx++)
                acc = fmaf(s_f[buf][ty+dy][tx+dx], kl[dy*KK+dx], acc);
        ob[c*HWq + y*Wq + xx] = xb[c*HWq + y*Wq + xx] + acc;
    }
}

// ---------------------------------------------------------------------------
extern "C" void kernel_launch(void* const* d_in, const int* in_sizes, int n_in,
                              void* d_out, int out_size)
{
    const float* x   = (const float*)d_in[0];
    const float* kf  = (const float*)d_in[1];
    const float* fw1 = (const float*)d_in[2];
    const float* fb1 = (const float*)d_in[3];
    const float* fw2 = (const float*)d_in[4];
    const float* fb2 = (const float*)d_in[5];
    const float* mw1 = (const float*)d_in[6];
    const float* mb1 = (const float*)d_in[7];
    const float* mw2 = (const float*)d_in[8];
    const float* mb2 = (const float*)d_in[9];
    const float* lw1 = (const float*)d_in[10];
    const float* lb1 = (const float*)d_in[11];
    const float* lw2 = (const float*)d_in[12];
    const float* lb2 = (const float*)d_in[13];
    float* out = (float*)d_out;

    float *rxp, *b1fp, *b1mp, *b2fp, *b2mp, *ftp, *lpp;
    float2* wBp;
    cudaGetSymbolAddress((void**)&rxp,  g_rx);
    cudaGetSymbolAddress((void**)&b1fp, g_b1f);
    cudaGetSymbolAddress((void**)&b1mp, g_b1m);
    cudaGetSymbolAddress((void**)&b2fp, g_b2f);
    cudaGetSymbolAddress((void**)&b2mp, g_b2m);
    cudaGetSymbolAddress((void**)&ftp,  g_ft);
    cudaGetSymbolAddress((void**)&lpp,  g_lp);
    cudaGetSymbolAddress((void**)&wBp,  g_wB2);

    dim3 cblk(256);
    prep_relu_kernel<<<(Bq*CHWq/4)/256, cblk>>>(x, rxp);
    prep_wt_kernel<<<(4*WB2_CONV)/256, cblk>>>(fw1, fw2, mw1, mw2, wBp);
    lp_kernel<<<(Bq*HWq)/256, cblk>>>(kf, lw1, lb1, lw2, lb2, lpp);

    dim3 tgrid(Hq, 2*Bq);   // 1024 CTAs per stage
    const float2* wf1 = wBp + 0*WB2_CONV;
    const float2* wf2 = wBp + 1*WB2_CONV;
    const float2* wm1 = wBp + 2*WB2_CONV;
    const float2* wm2 = wBp + 3*WB2_CONV;

    conv_mma_kernel<true><<<tgrid, cblk>>>(
        rxp, kf, wf1, wm1, fb1, mb1, b1fp, b1mp);
    conv_mma_kernel<false><<<tgrid, cblk>>>(
        b1fp, b1mp, wf2, wm2, fb2, mb2, b2fp, b2mp);

    // feat = fp * mp
    prep_mul_kernel<<<(Bq*CHWq/4)/256, cblk>>>(b2fp, b2mp, ftp);

    dim3 lgrid(Wq/TILE, Hq/TILE, Bq*LC_CG);
    local_conv_kernel<<<lgrid, cblk>>>(x, ftp, lpp, out);
}

// round 11
// speedup vs baseline: 2.4404x; 1.2168x over previous
#include <cuda_runtime.h>
#include <cstdint>

#define Bq 4
#define Cq 64
#define Hq 128
#define Wq 128
#define HWq (Hq*Wq)
#define CHWq (Cq*HWq)
#define HW8 (HWq*8)
#define KK 7
#define TAPS 49
#define NGRP 24                 // (dy 3) x (oct 8)
#define NKB  72
#define WB2_CONV (NKB*256)

// scratch (allocation-free rule: __device__ globals). NHWC8 layout for all
// intermediates: [b][oct][y][x][ci_in_oct(8)].
__device__ float  g_rx [Bq*CHWq];
__device__ float  g_kf [Bq*CHWq];
__device__ float  g_b1f[Bq*CHWq];
__device__ float  g_b1m[Bq*CHWq];
__device__ float  g_b2f[Bq*CHWq];
__device__ float  g_b2m[Bq*CHWq];
__device__ float  g_ft [Bq*CHWq];
__device__ float  g_lp [Bq*TAPS*HWq];
__device__ float2 g_wB2[4*WB2_CONV];

// ---------------------------------------------------------------------------
__device__ __forceinline__ uint32_t tf32_hi(float v) {
    uint32_t r; asm("cvt.rna.tf32.f32 %0, %1;" : "=r"(r) : "f"(v)); return r;
}
__device__ __forceinline__ void cp16(void* dst, const void* src) {
    unsigned d = (unsigned)__cvta_generic_to_shared(dst);
    asm volatile("cp.async.ca.shared.global [%0], [%1], 16;" :: "r"(d), "l"(src));
}
#define CP_COMMIT asm volatile("cp.async.commit_group;")
#define CP_WAIT0  asm volatile("cp.async.wait_group 0;")

__device__ __forceinline__ void mma_tf32(float d[4], const uint32_t a[4],
                                         uint32_t b0, uint32_t b1)
{
    asm volatile(
        "mma.sync.aligned.m16n8k8.row.col.f32.tf32.tf32.f32 "
        "{%0,%1,%2,%3}, {%4,%5,%6,%7}, {%8,%9}, {%0,%1,%2,%3};"
        : "+f"(d[0]), "+f"(d[1]), "+f"(d[2]), "+f"(d[3])
        : "r"(a[0]), "r"(a[1]), "r"(a[2]), "r"(a[3]), "r"(b0), "r"(b1));
}
__device__ __forceinline__ unsigned long long dup2(float a) {
    unsigned long long r;
    asm("mov.b64 %0, {%1, %1};" : "=l"(r) : "f"(a)); return r;
}
__device__ __forceinline__ void fma2(unsigned long long& d,
                                     unsigned long long a, unsigned long long b) {
    asm("fma.rn.f32x2 %0, %1, %2, %0;" : "+l"(d) : "l"(a), "l"(b));
}
__device__ __forceinline__ float2 unpack2(unsigned long long v) {
    float2 f;
    asm("mov.b64 {%0, %1}, %2;" : "=f"(f.x), "=f"(f.y) : "l"(v)); return f;
}

// ---------------------------------------------------------------------------
// prep: NCHW -> NHWC8 transpose (optional relu)
// ---------------------------------------------------------------------------
template<bool RELU>
__global__ void prep_nhwc8_kernel(const float* __restrict__ in, float* __restrict__ out)
{
    int i  = blockIdx.x*256 + threadIdx.x;     // (b*8+oct)*HWq + hw
    int hw = i & (HWq-1);
    int bo = i >> 14;
    const float* p = in + bo*8*HWq + hw;
    float v[8];
#pragma unroll
    for (int c = 0; c < 8; c++) {
        float t = p[c*HWq];
        v[c] = RELU ? fmaxf(t, 0.f) : t;
    }
    float4* o = (float4*)(out + (size_t)i*8);
    o[0] = make_float4(v[0], v[1], v[2], v[3]);
    o[1] = make_float4(v[4], v[5], v[6], v[7]);
}
__global__ void prep_mul_kernel(const float* __restrict__ a, const float* __restrict__ b,
                                float* __restrict__ o)
{
    int i = blockIdx.x*256 + threadIdx.x;
    float4 va = ((const float4*)a)[i];
    float4 vb = ((const float4*)b)[i];
    ((float4*)o)[i] = make_float4(va.x*vb.x, va.y*vb.y, va.z*vb.z, va.w*vb.w);
}

// Pack weights (unchanged layout): kb = (dy*8+oct)*3 + dx, hi plane only.
__global__ void prep_wt_kernel(const float* __restrict__ w0, const float* __restrict__ w1,
                               const float* __restrict__ w2, const float* __restrict__ w3,
                               float2* __restrict__ wB2)
{
    int i = blockIdx.x*256 + threadIdx.x;
    int conv = i / WB2_CONV;
    int r    = i - conv*WB2_CONV;
    int kb   = r >> 8;
    int r2   = r & 255;
    int nb   = r2 >> 5;
    int lane = r2 & 31;

    int g  = kb / 3, dx = kb - g*3;
    int dy = g >> 3, oct = g & 7;
    int tap = dy*3 + dx;
    int n   = nb*8 + (lane >> 2);
    int ci0 = oct*8 + (lane & 3);

    const float* w = (conv == 0) ? w0 : (conv == 1) ? w1 : (conv == 2) ? w2 : w3;
    float v0 = w[(n*Cq + ci0    )*9 + tap];
    float v1 = w[(n*Cq + ci0 + 4)*9 + tap];
    wB2[i] = make_float2(__uint_as_float(tf32_hi(v0)), __uint_as_float(tf32_hi(v1)));
}

// ---------------------------------------------------------------------------
// conv3x3 via mma.sync tf32 1-pass. NHWC8 in/out.
// CTA = 128 threads (4 warps), one output row: D[128 px][64 co].
// Warp = 32 px x 64 co (mi 0..1, ni 0..7). grid (Hq, 2*Bq).
// A smem: [buf][px 0..129][8], pair-swizzled (conflict-free, as R10).
// ---------------------------------------------------------------------------
template<bool RELU_OUT>
__global__ __launch_bounds__(128, 4)
void conv_mma_kernel(const float* __restrict__ inA, const float* __restrict__ inB,
                     const float2* __restrict__ wBA, const float2* __restrict__ wBB,
                     const float* __restrict__ biasA, const float* __restrict__ biasB,
                     float* __restrict__ outA, float* __restrict__ outB)
{
    __shared__ alignas(16) float  sA[2][130*8];
    __shared__ alignas(16) float2 sB[2][768];

    const int y  = blockIdx.x;
    const int z  = blockIdx.y;
    const int b  = z & 3;
    const bool pB = (z >= 4);
    const float*  in   = (pB ? inB  : inA) + b*CHWq;
    const float2* wB   =  pB ? wBB  : wBA;
    const float*  bias =  pB ? biasB : biasA;
    float*        out  = (pB ? outB : outA) + b*CHWq;

    const int tid  = threadIdx.x;
    const int wid  = tid >> 5;      // 0..3 = mw
    const int lane = tid & 31;

    if (tid < 32) {
        int bb = tid >> 4, rr = (tid >> 3) & 1, cc = tid & 7;
        sA[bb][(rr ? 129*8 : 0) + cc] = 0.f;
    }

    float d[2][8][4];
#pragma unroll
    for (int mi = 0; mi < 2; mi++)
#pragma unroll
        for (int ni = 0; ni < 8; ni++)
#pragma unroll
            for (int r = 0; r < 4; r++) d[mi][ni][r] = 0.f;

    float4 va, vb_;
    auto preloadA = [&](int g) {
        int dy = g >> 3, oct = g & 7;
        int yin = y + dy - 1;
        if (yin >= 0 && yin < Hq) {
            const float4* p = (const float4*)(in + oct*HW8 + (yin*Wq + tid)*8);
            va  = __ldg(p);
            vb_ = __ldg(p + 1);
        } else {
            va  = make_float4(0.f, 0.f, 0.f, 0.f);
            vb_ = make_float4(0.f, 0.f, 0.f, 0.f);
        }
    };
    auto storeA = [&](int buf) {
        int px = tid + 1;
        int sw = (px >> 2) & 1;
        float* base = &sA[buf][px*8];
        float4 p0 = make_float4(__uint_as_float(tf32_hi(va.x)),
                                __uint_as_float(tf32_hi(vb_.x)),
                                __uint_as_float(tf32_hi(va.y)),
                                __uint_as_float(tf32_hi(vb_.y)));
        float4 p1 = make_float4(__uint_as_float(tf32_hi(va.z)),
                                __uint_as_float(tf32_hi(vb_.z)),
                                __uint_as_float(tf32_hi(va.w)),
                                __uint_as_float(tf32_hi(vb_.w)));
        *(float4*)(base + ((0 ^ sw) << 2)) = p0;
        *(float4*)(base + ((1 ^ sw) << 2)) = p1;
    };
    auto stageB = [&](int buf, int g) {
        const float4* src = (const float4*)(wB + g*768);
        float4* dst = (float4*)sB[buf];
        cp16(dst + tid,       src + tid);
        cp16(dst + 128 + tid, src + 128 + tid);
        cp16(dst + 256 + tid, src + 256 + tid);
        CP_COMMIT;
    };

    preloadA(0);
    storeA(0);
    stageB(0, 0);

    for (int g = 0; g < NGRP; g++) {
        const int buf = g & 1;
        CP_WAIT0;
        __syncthreads();
        if (g + 1 < NGRP) { stageB(buf ^ 1, g + 1); preloadA(g + 1); }

#pragma unroll
        for (int dx = 0; dx < 3; dx++) {
            uint32_t a[2][4];
#pragma unroll
            for (int mi = 0; mi < 2; mi++) {
                int pxl = wid*32 + mi*16 + (lane >> 2) + dx;
                int c   = lane & 3;
                int sw  = (pxl >> 2) & 1;
                int off = (((c >> 1) ^ sw) << 2) + ((c & 1) << 1);
                float2 q0 = *(float2*)&sA[buf][pxl*8 + off];
                float2 q1 = *(float2*)&sA[buf][(pxl + 8)*8 + off];
                a[mi][0] = __float_as_uint(q0.x);
                a[mi][2] = __float_as_uint(q0.y);
                a[mi][1] = __float_as_uint(q1.x);
                a[mi][3] = __float_as_uint(q1.y);
            }
#pragma unroll
            for (int ni = 0; ni < 8; ni++) {
                float2 bq = sB[buf][(dx*8 + ni)*32 + lane];
                uint32_t b0 = __float_as_uint(bq.x), b1 = __float_as_uint(bq.y);
#pragma unroll
                for (int mi = 0; mi < 2; mi++)
                    mma_tf32(d[mi][ni], a[mi], b0, b1);
            }
        }

        if (g + 1 < NGRP) storeA(buf ^ 1);
        __syncthreads();
    }

    // epilogue: NHWC8 out, coalesced STG.64
    const int row  = lane >> 2;
    const int colb = (lane & 3) << 1;
#pragma unroll
    for (int mi = 0; mi < 2; mi++) {
        int px0 = wid*32 + mi*16 + row;
#pragma unroll
        for (int ni = 0; ni < 8; ni++) {
            float b0 = __ldg(bias + ni*8 + colb);
            float b1 = __ldg(bias + ni*8 + colb + 1);
            float2 r0 = make_float2(d[mi][ni][0] + b0, d[mi][ni][1] + b1);
            float2 r1 = make_float2(d[mi][ni][2] + b0, d[mi][ni][3] + b1);
            if (RELU_OUT) {
                r0.x = fmaxf(r0.x, 0.f); r0.y = fmaxf(r0.y, 0.f);
                r1.x = fmaxf(r1.x, 0.f); r1.y = fmaxf(r1.y, 0.f);
            }
            float* o8 = out + ni*HW8;
            *(float2*)(o8 + (y*Wq + px0    )*8 + colb) = r0;
            *(float2*)(o8 + (y*Wq + px0 + 8)*8 + colb) = r1;
        }
    }
}

// ---------------------------------------------------------------------------
// local_filter_path, f32x2 packed: conv1x1(64->64) -> relu -> conv1x1(64->49)
// -> normalize. kf in NHWC8. One thread = one pixel.
// ---------------------------------------------------------------------------
__global__ __launch_bounds__(256, 1)
void lp_kernel(const float* __restrict__ kf,
               const float* __restrict__ w1, const float* __restrict__ b1,
               const float* __restrict__ w2, const float* __restrict__ b2,
               float* __restrict__ lp)
{
    __shared__ alignas(16) float s_w1[64*64];   // [ci][co]
    __shared__ alignas(16) float s_w2[64*52];   // [ci][k], pad zeroed
    __shared__ alignas(8)  float s_b1[64];
    __shared__ alignas(8)  float s_b2[52];
    const int tid = threadIdx.x;

    for (int i = tid; i < 64*64; i += 256) {
        int ci = i >> 6, co = i & 63;
        s_w1[i] = w1[co*64 + ci];
    }
    for (int i = tid; i < 64*52; i += 256) {
        int ci = i / 52, k = i - ci*52;
        s_w2[i] = (k < 49) ? w2[k*64 + ci] : 0.f;
    }
    if (tid < 64) s_b1[tid] = b1[tid];
    if (tid < 52) s_b2[tid] = (tid < 49) ? b2[tid] : 0.f;
    __syncthreads();

    const int p  = blockIdx.x*256 + tid;
    const int b  = p >> 14;
    const int hw = p & (HWq-1);
    const float* kfb = kf + b*CHWq;

    unsigned long long h2[32];
#pragma unroll
    for (int j = 0; j < 32; j++) h2[j] = ((const unsigned long long*)s_b1)[j];

    for (int oct = 0; oct < 8; oct++) {
        const float4* kp = (const float4*)(kfb + oct*HW8 + hw*8);
        float4 u0 = __ldg(kp), u1 = __ldg(kp + 1);
        float xv[8] = { u0.x, u0.y, u0.z, u0.w, u1.x, u1.y, u1.z, u1.w };
#pragma unroll
        for (int j = 0; j < 8; j++) {
            unsigned long long vd = dup2(xv[j]);
            const ulonglong2* wr = (const ulonglong2*)(s_w1 + (oct*8 + j)*64);
#pragma unroll
            for (int q = 0; q < 16; q++) {
                ulonglong2 wp = wr[q];
                fma2(h2[2*q],     wp.x, vd);
                fma2(h2[2*q + 1], wp.y, vd);
            }
        }
    }
    float h[64];
#pragma unroll
    for (int j = 0; j < 32; j++) {
        float2 f = unpack2(h2[j]);
        h[2*j]     = fmaxf(f.x, 0.f);
        h[2*j + 1] = fmaxf(f.y, 0.f);
    }

    unsigned long long o2[25];
#pragma unroll
    for (int j = 0; j < 25; j++) o2[j] = ((const unsigned long long*)s_b2)[j];
    for (int ci = 0; ci < 64; ci++) {
        unsigned long long vd = dup2(h[ci]);
        const ulonglong2* wr = (const ulonglong2*)(s_w2 + ci*52);
#pragma unroll
        for (int q = 0; q < 12; q++) {
            ulonglong2 wp = wr[q];
            fma2(o2[2*q],     wp.x, vd);
            fma2(o2[2*q + 1], wp.y, vd);
        }
        fma2(o2[24], ((const unsigned long long*)(s_w2 + ci*52))[24], vd);
    }

    float ov[50];
    float m = 0.f;
#pragma unroll
    for (int j = 0; j < 25; j++) {
        float2 f = unpack2(o2[j]);
        ov[2*j] = f.x; ov[2*j + 1] = f.y;
        m += f.x + f.y;               // ov[49] is pad == 0
    }
    m *= (1.0f/49.0f);

    float* lpp = lp + b*TAPS*HWq + hw;
#pragma unroll
    for (int k = 0; k < TAPS; k++)
        lpp[k*HWq] = ov[k] - m + (1.0f/49.0f);
}

// ---------------------------------------------------------------------------
// dynamic 7x7 local conv + residual. feat NHWC8, 8-channel tiles, f32x2,
// register-preload double buffering, 1 sync per oct. x/out NCHW.
// ---------------------------------------------------------------------------
#define TILE 16
__global__ __launch_bounds__(256, 2)
void local_conv_kernel(const float* __restrict__ x, const float* __restrict__ feat,
                       const float* __restrict__ lp, float* __restrict__ out)
{
    __shared__ alignas(16) float s_f[2][22*22*10];   // pad-10: conflict-free LDS.64
    const int b  = blockIdx.z;
    const int x0 = blockIdx.x * TILE;
    const int y0 = blockIdx.y * TILE;
    const int tid = threadIdx.x;
    const int tx = tid & 15, ty = tid >> 4;
    const int y = y0 + ty, xx = x0 + tx;

    float kl[TAPS];
    const float* lpp = lp + b*TAPS*HWq + y*Wq + xx;
#pragma unroll
    for (int k = 0; k < TAPS; k++) kl[k] = lpp[k*HWq];

    const float* fb = feat + b*CHWq;
    const float* xb = x    + b*CHWq;
    float*       ob = out  + b*CHWq;

    float4 pv[2][2];
    auto preloadF = [&](int oct) {
#pragma unroll
        for (int s = 0; s < 2; s++) {
            int idx = tid + s*256;
            if (idx < 484) {
                int r  = idx / 22;
                int cc = idx - r*22;
                int gy = y0 + r - 3, gx = x0 + cc - 3;
                if (gy >= 0 && gy < Hq && gx >= 0 && gx < Wq) {
                    const float4* p = (const float4*)(fb + oct*HW8 + (gy*Wq + gx)*8);
                    pv[s][0] = __ldg(p);
                    pv[s][1] = __ldg(p + 1);
                } else {
                    pv[s][0] = make_float4(0.f, 0.f, 0.f, 0.f);
                    pv[s][1] = make_float4(0.f, 0.f, 0.f, 0.f);
                }
            }
        }
    };
    auto storeF = [&](int buf) {
#pragma unroll
        for (int s = 0; s < 2; s++) {
            int idx = tid + s*256;
            if (idx < 484) {
                float* dst = &s_f[buf][idx*10];
                *(float2*)(dst + 0) = make_float2(pv[s][0].x, pv[s][0].y);
                *(float2*)(dst + 2) = make_float2(pv[s][0].z, pv[s][0].w);
                *(float2*)(dst + 4) = make_float2(pv[s][1].x, pv[s][1].y);
                *(float2*)(dst + 6) = make_float2(pv[s][1].z, pv[s][1].w);
            }
        }
    };

    preloadF(0);
    storeF(0);

    for (int oct = 0; oct < 8; oct++) {
        const int buf = oct & 1;
        __syncthreads();
        if (oct + 1 < 8) preloadF(oct + 1);

        unsigned long long acc2[4] = {0ULL, 0ULL, 0ULL, 0ULL};
#pragma unroll
        for (int dy = 0; dy < KK; dy++) {
#pragma unroll
            for (int dx = 0; dx < KK; dx++) {
                unsigned long long kd = dup2(kl[dy*KK + dx]);
                const unsigned long long* q =
                    (const unsigned long long*)&s_f[buf][((ty + dy)*22 + tx + dx)*10];
                fma2(acc2[0], q[0], kd);
                fma2(acc2[1], q[1], kd);
                fma2(acc2[2], q[2], kd);
                fma2(acc2[3], q[3], kd);
            }
        }

        if (oct + 1 < 8) storeF(buf ^ 1);

#pragma unroll
        for (int j = 0; j < 4; j++) {
            float2 f = unpack2(acc2[j]);
            int off0 = (oct*8 + 2*j)*HWq + y*Wq + xx;
            ob[off0]       = xb[off0]       + f.x;
            ob[off0 + HWq] = xb[off0 + HWq] + f.y;
        }
    }
}

// ---------------------------------------------------------------------------
extern "C" void kernel_launch(void* const* d_in, const int* in_sizes, int n_in,
                              void* d_out, int out_size)
{
    const float* x   = (const float*)d_in[0];
    const float* kf  = (const float*)d_in[1];
    const float* fw1 = (const float*)d_in[2];
    const float* fb1 = (const float*)d_in[3];
    const float* fw2 = (const float*)d_in[4];
    const float* fb2 = (const float*)d_in[5];
    const float* mw1 = (const float*)d_in[6];
    const float* mb1 = (const float*)d_in[7];
    const float* mw2 = (const float*)d_in[8];
    const float* mb2 = (const float*)d_in[9];
    const float* lw1 = (const float*)d_in[10];
    const float* lb1 = (const float*)d_in[11];
    const float* lw2 = (const float*)d_in[12];
    const float* lb2 = (const float*)d_in[13];
    float* out = (float*)d_out;

    float *rxp, *kfp, *b1fp, *b1mp, *b2fp, *b2mp, *ftp, *lpp;
    float2* wBp;
    cudaGetSymbolAddress((void**)&rxp,  g_rx);
    cudaGetSymbolAddress((void**)&kfp,  g_kf);
    cudaGetSymbolAddress((void**)&b1fp, g_b1f);
    cudaGetSymbolAddress((void**)&b1mp, g_b1m);
    cudaGetSymbolAddress((void**)&b2fp, g_b2f);
    cudaGetSymbolAddress((void**)&b2mp, g_b2m);
    cudaGetSymbolAddress((void**)&ftp,  g_ft);
    cudaGetSymbolAddress((void**)&lpp,  g_lp);
    cudaGetSymbolAddress((void**)&wBp,  g_wB2);

    dim3 cblk(256);
    // NHWC8 transposes (relu fused for x)
    prep_nhwc8_kernel<true ><<<(Bq*8*HWq)/256, cblk>>>(x,  rxp);
    prep_nhwc8_kernel<false><<<(Bq*8*HWq)/256, cblk>>>(kf, kfp);
    prep_wt_kernel<<<(4*WB2_CONV)/256, cblk>>>(fw1, fw2, mw1, mw2, wBp);
    lp_kernel<<<(Bq*HWq)/256, cblk>>>(kfp, lw1, lb1, lw2, lb2, lpp);

    dim3 tgrid(Hq, 2*Bq);
    dim3 tblk(128);
    const float2* wf1 = wBp + 0*WB2_CONV;
    const float2* wf2 = wBp + 1*WB2_CONV;
    const float2* wm1 = wBp + 2*WB2_CONV;
    const float2* wm2 = wBp + 3*WB2_CONV;

    conv_mma_kernel<true ><<<tgrid, tblk>>>(
        rxp, kfp, wf1, wm1, fb1, mb1, b1fp, b1mp);
    conv_mma_kernel<false><<<tgrid, tblk>>>(
        b1fp, b1mp, wf2, wm2, fb2, mb2, b2fp, b2mp);

    prep_mul_kernel<<<(Bq*CHWq/4)/256, cblk>>>(b2fp, b2mp, ftp);

    dim3 lgrid(Wq/TILE, Hq/TILE, Bq);
    local_conv_kernel<<<lgrid, cblk>>>(x, ftp, lpp, out);
}

// round 12
// speedup vs baseline: 2.7769x; 1.1379x over previous
#include <cuda_runtime.h>
#include <cstdint>

#define Bq 4
#define Cq 64
#define Hq 128
#define Wq 128
#define HWq (Hq*Wq)
#define CHWq (Cq*HWq)
#define HW8 (HWq*8)
#define KK 7
#define TAPS 49
#define NGRP 24
#define NKB  72
#define WB2_CONV (NKB*256)

// scratch (allocation-free rule: __device__ globals). NHWC8 for intermediates.
__device__ float  g_rx [Bq*CHWq];
__device__ float  g_kf [Bq*CHWq];
__device__ float  g_b1f[Bq*CHWq];
__device__ float  g_b1m[Bq*CHWq];
__device__ float  g_b2f[Bq*CHWq];
__device__ float  g_b2m[Bq*CHWq];
__device__ float  g_ft [Bq*CHWq];
__device__ float  g_lp [Bq*HWq*52];     // [b][hw][52] tap-innermost
__device__ float2 g_wB2[4*WB2_CONV];
__device__ float2 g_wL1[2048];          // lp GEMM1 B frags
__device__ float2 g_wL2[1792];          // lp GEMM2 B frags

// ---------------------------------------------------------------------------
__device__ __forceinline__ uint32_t tf32_hi(float v) {
    uint32_t r; asm("cvt.rna.tf32.f32 %0, %1;" : "=r"(r) : "f"(v)); return r;
}
__device__ __forceinline__ float tf32f(float v) {
    return __uint_as_float(tf32_hi(v));
}
__device__ __forceinline__ void cp16(void* dst, const void* src) {
    unsigned d = (unsigned)__cvta_generic_to_shared(dst);
    asm volatile("cp.async.ca.shared.global [%0], [%1], 16;" :: "r"(d), "l"(src));
}
#define CP_COMMIT asm volatile("cp.async.commit_group;")
#define CP_WAIT0  asm volatile("cp.async.wait_group 0;")

__device__ __forceinline__ void mma_tf32(float d[4], const uint32_t a[4],
                                         uint32_t b0, uint32_t b1)
{
    asm volatile(
        "mma.sync.aligned.m16n8k8.row.col.f32.tf32.tf32.f32 "
        "{%0,%1,%2,%3}, {%4,%5,%6,%7}, {%8,%9}, {%0,%1,%2,%3};"
        : "+f"(d[0]), "+f"(d[1]), "+f"(d[2]), "+f"(d[3])
        : "r"(a[0]), "r"(a[1]), "r"(a[2]), "r"(a[3]), "r"(b0), "r"(b1));
}
__device__ __forceinline__ unsigned long long dup2(float a) {
    unsigned long long r;
    asm("mov.b64 %0, {%1, %1};" : "=l"(r) : "f"(a)); return r;
}
__device__ __forceinline__ void fma2(unsigned long long& d,
                                     unsigned long long a, unsigned long long b) {
    asm("fma.rn.f32x2 %0, %1, %2, %0;" : "+l"(d) : "l"(a), "l"(b));
}
__device__ __forceinline__ float2 unpack2(unsigned long long v) {
    float2 f;
    asm("mov.b64 {%0, %1}, %2;" : "=f"(f.x), "=f"(f.y) : "l"(v)); return f;
}

// ---------------------------------------------------------------------------
// prep kernels
// ---------------------------------------------------------------------------
template<bool RELU>
__global__ void prep_nhwc8_kernel(const float* __restrict__ in, float* __restrict__ out)
{
    int i  = blockIdx.x*256 + threadIdx.x;
    int hw = i & (HWq-1);
    int bo = i >> 14;
    const float* p = in + bo*8*HWq + hw;
    float v[8];
#pragma unroll
    for (int c = 0; c < 8; c++) {
        float t = p[c*HWq];
        v[c] = RELU ? fmaxf(t, 0.f) : t;
    }
    float4* o = (float4*)(out + (size_t)i*8);
    o[0] = make_float4(v[0], v[1], v[2], v[3]);
    o[1] = make_float4(v[4], v[5], v[6], v[7]);
}
__global__ void prep_mul_kernel(const float* __restrict__ a, const float* __restrict__ b,
                                float* __restrict__ o)
{
    int i = blockIdx.x*256 + threadIdx.x;
    float4 va = ((const float4*)a)[i];
    float4 vb = ((const float4*)b)[i];
    ((float4*)o)[i] = make_float4(va.x*vb.x, va.y*vb.y, va.z*vb.z, va.w*vb.w);
}
__global__ void prep_wt_kernel(const float* __restrict__ w0, const float* __restrict__ w1,
                               const float* __restrict__ w2, const float* __restrict__ w3,
                               float2* __restrict__ wB2)
{
    int i = blockIdx.x*256 + threadIdx.x;
    int conv = i / WB2_CONV;
    int r    = i - conv*WB2_CONV;
    int kb   = r >> 8;
    int r2   = r & 255;
    int nb   = r2 >> 5;
    int lane = r2 & 31;

    int g  = kb / 3, dx = kb - g*3;
    int dy = g >> 3, oct = g & 7;
    int tap = dy*3 + dx;
    int n   = nb*8 + (lane >> 2);
    int ci0 = oct*8 + (lane & 3);

    const float* w = (conv == 0) ? w0 : (conv == 1) ? w1 : (conv == 2) ? w2 : w3;
    float v0 = w[(n*Cq + ci0    )*9 + tap];
    float v1 = w[(n*Cq + ci0 + 4)*9 + tap];
    wB2[i] = make_float2(tf32f(v0), tf32f(v1));
}
// lp-path weight frags: wL1 (64->64), wL2 (64->49 padded to 56)
__global__ void prep_lpwt_kernel(const float* __restrict__ w1, const float* __restrict__ w2,
                                 float2* __restrict__ wL1, float2* __restrict__ wL2)
{
    int i = blockIdx.x*256 + threadIdx.x;
    if (i < 2048) {
        int kb = i >> 8, r2 = i & 255, nb = r2 >> 5, lane = r2 & 31;
        int n = nb*8 + (lane >> 2), ci = kb*8 + (lane & 3);
        wL1[i] = make_float2(tf32f(w1[n*64 + ci]), tf32f(w1[n*64 + ci + 4]));
    } else if (i < 3840) {
        int j = i - 2048;
        int kb = j / 224, r2 = j - kb*224, nb = r2 >> 5, lane = r2 & 31;
        int n = nb*8 + (lane >> 2), ci = kb*8 + (lane & 3);
        float v0 = (n < 49) ? w2[n*64 + ci]     : 0.f;
        float v1 = (n < 49) ? w2[n*64 + ci + 4] : 0.f;
        wL2[j] = make_float2(tf32f(v0), tf32f(v1));
    }
}

// ---------------------------------------------------------------------------
// conv3x3 via mma.sync tf32 1-pass. NHWC8 in/out. (unchanged from R11)
// ---------------------------------------------------------------------------
template<bool RELU_OUT>
__global__ __launch_bounds__(128, 4)
void conv_mma_kernel(const float* __restrict__ inA, const float* __restrict__ inB,
                     const float2* __restrict__ wBA, const float2* __restrict__ wBB,
                     const float* __restrict__ biasA, const float* __restrict__ biasB,
                     float* __restrict__ outA, float* __restrict__ outB)
{
    __shared__ alignas(16) float  sA[2][130*8];
    __shared__ alignas(16) float2 sB[2][768];

    const int y  = blockIdx.x;
    const int z  = blockIdx.y;
    const int b  = z & 3;
    const bool pB = (z >= 4);
    const float*  in   = (pB ? inB  : inA) + b*CHWq;
    const float2* wB   =  pB ? wBB  : wBA;
    const float*  bias =  pB ? biasB : biasA;
    float*        out  = (pB ? outB : outA) + b*CHWq;

    const int tid  = threadIdx.x;
    const int wid  = tid >> 5;
    const int lane = tid & 31;

    if (tid < 32) {
        int bb = tid >> 4, rr = (tid >> 3) & 1, cc = tid & 7;
        sA[bb][(rr ? 129*8 : 0) + cc] = 0.f;
    }

    float d[2][8][4];
#pragma unroll
    for (int mi = 0; mi < 2; mi++)
#pragma unroll
        for (int ni = 0; ni < 8; ni++)
#pragma unroll
            for (int r = 0; r < 4; r++) d[mi][ni][r] = 0.f;

    float4 va, vb_;
    auto preloadA = [&](int g) {
        int dy = g >> 3, oct = g & 7;
        int yin = y + dy - 1;
        if (yin >= 0 && yin < Hq) {
            const float4* p = (const float4*)(in + oct*HW8 + (yin*Wq + tid)*8);
            va  = __ldg(p);
            vb_ = __ldg(p + 1);
        } else {
            va  = make_float4(0.f, 0.f, 0.f, 0.f);
            vb_ = make_float4(0.f, 0.f, 0.f, 0.f);
        }
    };
    auto storeA = [&](int buf) {
        int px = tid + 1;
        int sw = (px >> 2) & 1;
        float* base = &sA[buf][px*8];
        float4 p0 = make_float4(tf32f(va.x), tf32f(vb_.x), tf32f(va.y), tf32f(vb_.y));
        float4 p1 = make_float4(tf32f(va.z), tf32f(vb_.z), tf32f(va.w), tf32f(vb_.w));
        *(float4*)(base + ((0 ^ sw) << 2)) = p0;
        *(float4*)(base + ((1 ^ sw) << 2)) = p1;
    };
    auto stageB = [&](int buf, int g) {
        const float4* src = (const float4*)(wB + g*768);
        float4* dst = (float4*)sB[buf];
        cp16(dst + tid,       src + tid);
        cp16(dst + 128 + tid, src + 128 + tid);
        cp16(dst + 256 + tid, src + 256 + tid);
        CP_COMMIT;
    };

    preloadA(0);
    storeA(0);
    stageB(0, 0);

    for (int g = 0; g < NGRP; g++) {
        const int buf = g & 1;
        CP_WAIT0;
        __syncthreads();
        if (g + 1 < NGRP) { stageB(buf ^ 1, g + 1); preloadA(g + 1); }

#pragma unroll
        for (int dx = 0; dx < 3; dx++) {
            uint32_t a[2][4];
#pragma unroll
            for (int mi = 0; mi < 2; mi++) {
                int pxl = wid*32 + mi*16 + (lane >> 2) + dx;
                int c   = lane & 3;
                int sw  = (pxl >> 2) & 1;
                int off = (((c >> 1) ^ sw) << 2) + ((c & 1) << 1);
                float2 q0 = *(float2*)&sA[buf][pxl*8 + off];
                float2 q1 = *(float2*)&sA[buf][(pxl + 8)*8 + off];
                a[mi][0] = __float_as_uint(q0.x);
                a[mi][2] = __float_as_uint(q0.y);
                a[mi][1] = __float_as_uint(q1.x);
                a[mi][3] = __float_as_uint(q1.y);
            }
#pragma unroll
            for (int ni = 0; ni < 8; ni++) {
                float2 bq = sB[buf][(dx*8 + ni)*32 + lane];
                uint32_t b0 = __float_as_uint(bq.x), b1 = __float_as_uint(bq.y);
#pragma unroll
                for (int mi = 0; mi < 2; mi++)
                    mma_tf32(d[mi][ni], a[mi], b0, b1);
            }
        }

        if (g + 1 < NGRP) storeA(buf ^ 1);
        __syncthreads();
    }

    const int row  = lane >> 2;
    const int colb = (lane & 3) << 1;
#pragma unroll
    for (int mi = 0; mi < 2; mi++) {
        int px0 = wid*32 + mi*16 + row;
#pragma unroll
        for (int ni = 0; ni < 8; ni++) {
            float b0 = __ldg(bias + ni*8 + colb);
            float b1 = __ldg(bias + ni*8 + colb + 1);
            float2 r0 = make_float2(d[mi][ni][0] + b0, d[mi][ni][1] + b1);
            float2 r1 = make_float2(d[mi][ni][2] + b0, d[mi][ni][3] + b1);
            if (RELU_OUT) {
                r0.x = fmaxf(r0.x, 0.f); r0.y = fmaxf(r0.y, 0.f);
                r1.x = fmaxf(r1.x, 0.f); r1.y = fmaxf(r1.y, 0.f);
            }
            float* o8 = out + ni*HW8;
            *(float2*)(o8 + (y*Wq + px0    )*8 + colb) = r0;
            *(float2*)(o8 + (y*Wq + px0 + 8)*8 + colb) = r1;
        }
    }
}

// ---------------------------------------------------------------------------
// lp path via mma.sync tf32: GEMM1 [128px,64]x[64,64] -> relu -> GEMM2
// [128px,64]x[64,56] -> normalize -> g_lp[hw][52]. CTA = 1 row, 128 thr.
// A + h share a 32KB pair-swizzled smem union (h overwrites A after GEMM1).
// ---------------------------------------------------------------------------
__global__ __launch_bounds__(128, 3)
void lp_mma_kernel(const float* __restrict__ kf,
                   const float2* __restrict__ wL1, const float2* __restrict__ wL2,
                   const float* __restrict__ b1, const float* __restrict__ b2,
                   float* __restrict__ lp)
{
    __shared__ alignas(16) float sU[8192];   // 32KB: A1, then h
    __shared__ float s_b1[64];
    __shared__ float s_b2[56];

    const int y = blockIdx.x, b = blockIdx.y;
    const int tid = threadIdx.x, wid = tid >> 5, lane = tid & 31;
    const float* kfb = kf + b*CHWq;

    if (tid < 64) s_b1[tid] = b1[tid];
    if (tid < 56) s_b2[tid] = (tid < 49) ? b2[tid] : 0.f;

    // stage A1 (kf row, all 8 octs), pair-swizzled
    {
        int px = tid, sw = (px >> 2) & 1;
#pragma unroll
        for (int oct = 0; oct < 8; oct++) {
            const float4* p = (const float4*)(kfb + oct*HW8 + (y*Wq + px)*8);
            float4 u0 = __ldg(p), u1 = __ldg(p + 1);
            float* base = &sU[oct*1024 + px*8];
            float4 p0 = make_float4(tf32f(u0.x), tf32f(u1.x), tf32f(u0.y), tf32f(u1.y));
            float4 p1 = make_float4(tf32f(u0.z), tf32f(u1.z), tf32f(u0.w), tf32f(u1.w));
            *(float4*)(base + ((0 ^ sw) << 2)) = p0;
            *(float4*)(base + ((1 ^ sw) << 2)) = p1;
        }
    }
    __syncthreads();

    // GEMM1
    float d1[2][8][4];
#pragma unroll
    for (int mi = 0; mi < 2; mi++)
#pragma unroll
        for (int ni = 0; ni < 8; ni++)
#pragma unroll
            for (int r = 0; r < 4; r++) d1[mi][ni][r] = 0.f;

#pragma unroll
    for (int oct = 0; oct < 8; oct++) {
        uint32_t a[2][4];
#pragma unroll
        for (int mi = 0; mi < 2; mi++) {
            int pxl = wid*32 + mi*16 + (lane >> 2);
            int c = lane & 3, sw = (pxl >> 2) & 1;
            int off = (((c >> 1) ^ sw) << 2) + ((c & 1) << 1);
            float2 q0 = *(float2*)&sU[oct*1024 + pxl*8 + off];
            float2 q1 = *(float2*)&sU[oct*1024 + (pxl + 8)*8 + off];
            a[mi][0] = __float_as_uint(q0.x);
            a[mi][2] = __float_as_uint(q0.y);
            a[mi][1] = __float_as_uint(q1.x);
            a[mi][3] = __float_as_uint(q1.y);
        }
#pragma unroll
        for (int ni = 0; ni < 8; ni++) {
            float2 bq = __ldg(&wL1[(oct*8 + ni)*32 + lane]);
            uint32_t b0 = __float_as_uint(bq.x), b1v = __float_as_uint(bq.y);
#pragma unroll
            for (int mi = 0; mi < 2; mi++)
                mma_tf32(d1[mi][ni], a[mi], b0, b1v);
        }
    }
    __syncthreads();   // all A1 reads done; reuse sU for h

    // write h = tf32(relu(d1 + b1)) into pair-swizzled layout (oct = ni)
    {
        const int colb = (lane & 3) << 1;
#pragma unroll
        for (int mi = 0; mi < 2; mi++) {
            int row0 = wid*32 + mi*16 + (lane >> 2);
            int sw   = (row0 >> 2) & 1;
            int blk  = ((((colb & 3) >> 1) ^ sw) << 2);
            int posE = blk + (colb >= 4 ? 1 : 0);
            int posO = blk + 2 + (colb >= 4 ? 1 : 0);
#pragma unroll
            for (int ni = 0; ni < 8; ni++) {
                float bA = s_b1[ni*8 + colb], bB = s_b1[ni*8 + colb + 1];
                float* base = &sU[ni*1024];
                base[row0*8 + posE]       = tf32f(fmaxf(d1[mi][ni][0] + bA, 0.f));
                base[row0*8 + posO]       = tf32f(fmaxf(d1[mi][ni][1] + bB, 0.f));
                base[(row0 + 8)*8 + posE] = tf32f(fmaxf(d1[mi][ni][2] + bA, 0.f));
                base[(row0 + 8)*8 + posO] = tf32f(fmaxf(d1[mi][ni][3] + bB, 0.f));
            }
        }
    }
    __syncthreads();

    // GEMM2
    float d2[2][7][4];
#pragma unroll
    for (int mi = 0; mi < 2; mi++)
#pragma unroll
        for (int ni = 0; ni < 7; ni++)
#pragma unroll
            for (int r = 0; r < 4; r++) d2[mi][ni][r] = 0.f;

#pragma unroll
    for (int oct = 0; oct < 8; oct++) {
        uint32_t a[2][4];
#pragma unroll
        for (int mi = 0; mi < 2; mi++) {
            int pxl = wid*32 + mi*16 + (lane >> 2);
            int c = lane & 3, sw = (pxl >> 2) & 1;
            int off = (((c >> 1) ^ sw) << 2) + ((c & 1) << 1);
            float2 q0 = *(float2*)&sU[oct*1024 + pxl*8 + off];
            float2 q1 = *(float2*)&sU[oct*1024 + (pxl + 8)*8 + off];
            a[mi][0] = __float_as_uint(q0.x);
            a[mi][2] = __float_as_uint(q0.y);
            a[mi][1] = __float_as_uint(q1.x);
            a[mi][3] = __float_as_uint(q1.y);
        }
#pragma unroll
        for (int ni = 0; ni < 7; ni++) {
            float2 bq = __ldg(&wL2[(oct*7 + ni)*32 + lane]);
            uint32_t b0 = __float_as_uint(bq.x), b1v = __float_as_uint(bq.y);
#pragma unroll
            for (int mi = 0; mi < 2; mi++)
                mma_tf32(d2[mi][ni], a[mi], b0, b1v);
        }
    }

    // epilogue: bias + mean-normalize + write [hw][52]
    const int colb = (lane & 3) << 1;
    float* lpb = lp + (size_t)(b*HWq + y*Wq)*52;
#pragma unroll
    for (int mi = 0; mi < 2; mi++) {
#pragma unroll
        for (int rh = 0; rh < 2; rh++) {
            int px = wid*32 + mi*16 + (lane >> 2) + rh*8;
            float v[7][2];
            float ls = 0.f;
#pragma unroll
            for (int ni = 0; ni < 7; ni++) {
                int col = ni*8 + colb;
                v[ni][0] = d2[mi][ni][rh*2 + 0] + s_b2[col];
                v[ni][1] = d2[mi][ni][rh*2 + 1] + s_b2[col + 1];
                ls += v[ni][0] + v[ni][1];
            }
            ls += __shfl_xor_sync(0xffffffff, ls, 1);
            ls += __shfl_xor_sync(0xffffffff, ls, 2);
            float m = ls * (1.0f/49.0f);
            float* rowp = lpb + (size_t)px*52;
#pragma unroll
            for (int ni = 0; ni < 7; ni++) {
                int col = ni*8 + colb;
                if (col < 52) {
                    float2 o = make_float2(v[ni][0] - m + (1.0f/49.0f),
                                           v[ni][1] - m + (1.0f/49.0f));
                    *(float2*)(rowp + col) = o;
                }
            }
        }
    }
}

// ---------------------------------------------------------------------------
// dynamic 7x7 local conv + residual. feat NHWC8; kl loaded via LDG.128 from
// tap-innermost g_lp. f32x2 FMAs, register double-buffering, 1 sync/oct.
// ---------------------------------------------------------------------------
#define TILE 16
__global__ __launch_bounds__(256, 2)
void local_conv_kernel(const float* __restrict__ x, const float* __restrict__ feat,
                       const float* __restrict__ lp, float* __restrict__ out)
{
    __shared__ alignas(16) float s_f[2][22*22*10];
    const int b  = blockIdx.z;
    const int x0 = blockIdx.x * TILE;
    const int y0 = blockIdx.y * TILE;
    const int tid = threadIdx.x;
    const int tx = tid & 15, ty = tid >> 4;
    const int y = y0 + ty, xx = x0 + tx;

    float kl[TAPS];
    {
        const float4* klb = (const float4*)(lp + (size_t)(b*HWq + y*Wq + xx)*52);
        float4 t[13];
#pragma unroll
        for (int q = 0; q < 13; q++) t[q] = __ldg(klb + q);
#pragma unroll
        for (int k = 0; k < TAPS; k++) kl[k] = ((const float*)t)[k];
    }

    const float* fb = feat + b*CHWq;
    const float* xb = x    + b*CHWq;
    float*       ob = out  + b*CHWq;

    float4 pv[2][2];
    auto preloadF = [&](int oct) {
#pragma unroll
        for (int s = 0; s < 2; s++) {
            int idx = tid + s*256;
            if (idx < 484) {
                int r  = idx / 22;
                int cc = idx - r*22;
                int gy = y0 + r - 3, gx = x0 + cc - 3;
                if (gy >= 0 && gy < Hq && gx >= 0 && gx < Wq) {
                    const float4* p = (const float4*)(fb + oct*HW8 + (gy*Wq + gx)*8);
                    pv[s][0] = __ldg(p);
                    pv[s][1] = __ldg(p + 1);
                } else {
                    pv[s][0] = make_float4(0.f, 0.f, 0.f, 0.f);
                    pv[s][1] = make_float4(0.f, 0.f, 0.f, 0.f);
                }
            }
        }
    };
    auto storeF = [&](int buf) {
#pragma unroll
        for (int s = 0; s < 2; s++) {
            int idx = tid + s*256;
            if (idx < 484) {
                float* dst = &s_f[buf][idx*10];
                *(float2*)(dst + 0) = make_float2(pv[s][0].x, pv[s][0].y);
                *(float2*)(dst + 2) = make_float2(pv[s][0].z, pv[s][0].w);
                *(float2*)(dst + 4) = make_float2(pv[s][1].x, pv[s][1].y);
                *(float2*)(dst + 6) = make_float2(pv[s][1].z, pv[s][1].w);
            }
        }
    };

    preloadF(0);
    storeF(0);

    for (int oct = 0; oct < 8; oct++) {
        const int buf = oct & 1;
        __syncthreads();
        if (oct + 1 < 8) preloadF(oct + 1);

        unsigned long long acc2[4] = {0ULL, 0ULL, 0ULL, 0ULL};
#pragma unroll
        for (int dy = 0; dy < KK; dy++) {
#pragma unroll
            for (int dx = 0; dx < KK; dx++) {
                unsigned long long kd = dup2(kl[dy*KK + dx]);
                const unsigned long long* q =
                    (const unsigned long long*)&s_f[buf][((ty + dy)*22 + tx + dx)*10];
                fma2(acc2[0], q[0], kd);
                fma2(acc2[1], q[1], kd);
                fma2(acc2[2], q[2], kd);
                fma2(acc2[3], q[3], kd);
            }
        }

        if (oct + 1 < 8) storeF(buf ^ 1);

#pragma unroll
        for (int j = 0; j < 4; j++) {
            float2 f = unpack2(acc2[j]);
            int off0 = (oct*8 + 2*j)*HWq + y*Wq + xx;
            ob[off0]       = xb[off0]       + f.x;
            ob[off0 + HWq] = xb[off0 + HWq] + f.y;
        }
    }
}

// ---------------------------------------------------------------------------
extern "C" void kernel_launch(void* const* d_in, const int* in_sizes, int n_in,
                              void* d_out, int out_size)
{
    const float* x   = (const float*)d_in[0];
    const float* kf  = (const float*)d_in[1];
    const float* fw1 = (const float*)d_in[2];
    const float* fb1 = (const float*)d_in[3];
    const float* fw2 = (const float*)d_in[4];
    const float* fb2 = (const float*)d_in[5];
    const float* mw1 = (const float*)d_in[6];
    const float* mb1 = (const float*)d_in[7];
    const float* mw2 = (const float*)d_in[8];
    const float* mb2 = (const float*)d_in[9];
    const float* lw1 = (const float*)d_in[10];
    const float* lb1 = (const float*)d_in[11];
    const float* lw2 = (const float*)d_in[12];
    const float* lb2 = (const float*)d_in[13];
    float* out = (float*)d_out;

    float *rxp, *kfp, *b1fp, *b1mp, *b2fp, *b2mp, *ftp, *lpp;
    float2 *wBp, *wL1p, *wL2p;
    cudaGetSymbolAddress((void**)&rxp,  g_rx);
    cudaGetSymbolAddress((void**)&kfp,  g_kf);
    cudaGetSymbolAddress((void**)&b1fp, g_b1f);
    cudaGetSymbolAddress((void**)&b1mp, g_b1m);
    cudaGetSymbolAddress((void**)&b2fp, g_b2f);
    cudaGetSymbolAddress((void**)&b2mp, g_b2m);
    cudaGetSymbolAddress((void**)&ftp,  g_ft);
    cudaGetSymbolAddress((void**)&lpp,  g_lp);
    cudaGetSymbolAddress((void**)&wBp,  g_wB2);
    cudaGetSymbolAddress((void**)&wL1p, g_wL1);
    cudaGetSymbolAddress((void**)&wL2p, g_wL2);

    dim3 cblk(256);
    prep_nhwc8_kernel<true ><<<(Bq*8*HWq)/256, cblk>>>(x,  rxp);
    prep_nhwc8_kernel<false><<<(Bq*8*HWq)/256, cblk>>>(kf, kfp);
    prep_wt_kernel<<<(4*WB2_CONV)/256, cblk>>>(fw1, fw2, mw1, mw2, wBp);
    prep_lpwt_kernel<<<15, cblk>>>(lw1, lw2, wL1p, wL2p);

    lp_mma_kernel<<<dim3(Hq, Bq), 128>>>(kfp, wL1p, wL2p, lb1, lb2, lpp);

    dim3 tgrid(Hq, 2*Bq);
    dim3 tblk(128);
    const float2* wf1 = wBp + 0*WB2_CONV;
    const float2* wf2 = wBp + 1*WB2_CONV;
    const float2* wm1 = wBp + 2*WB2_CONV;
    const float2* wm2 = wBp + 3*WB2_CONV;

    conv_mma_kernel<true ><<<tgrid, tblk>>>(
        rxp, kfp, wf1, wm1, fb1, mb1, b1fp, b1mp);
    conv_mma_kernel<false><<<tgrid, tblk>>>(
        b1fp, b1mp, wf2, wm2, fb2, mb2, b2fp, b2mp);

    prep_mul_kernel<<<(Bq*CHWq/4)/256, cblk>>>(b2fp, b2mp, ftp);

    dim3 lgrid(Wq/TILE, Hq/TILE, Bq);
    local_conv_kernel<<<lgrid, cblk>>>(x, ftp, lpp, out);
}